// round 12
// baseline (speedup 1.0000x reference)
#include <cuda_runtime.h>
#include <cuda_fp16.h>
#include <math.h>
#include <stdint.h>

// ---------------------------------------------------------------------------
// DonutSwinLayer: B=16, H=W=64, C=512, NH=16, HD=32, WS=8, N=64, SS=4, MLP=2048
// Round 12: R11 base; attention sc matrix in half (12 blocks/SM), fused prepass.
// ---------------------------------------------------------------------------

#define NTOK   65536
#define CDIM   512
#define NHEADS 16
#define HDIM   32
#define SSH    4
#define MLPD   2048
#define QKVN   1536
#define TCH    33554432ULL          // NTOK*CDIM (halves per q/k/v plane)

#define BM 128
#define BN 128
#define BK 64
#define ROWB 144                    // bytes per smem row (72 halves, LDSM-safe)
#define A_OFF 0
#define B_OFF (BM * ROWB)           // 18432
#define STAGE_B ((BM + BN) * ROWB)  // 36864
#define NSTAGE 2
#define GEMM_SMEM (NSTAGE * STAGE_B)   // 73728

__device__ unsigned char g_scratch[(size_t)26 * NTOK * CDIM + (1u << 24)];

// ============================ helpers ======================================
__device__ __forceinline__ void cp_async16(uint32_t s, const void* g) {
    asm volatile("cp.async.cg.shared.global [%0], [%1], 16;" :: "r"(s), "l"(g));
}
__device__ __forceinline__ void cp_commit() {
    asm volatile("cp.async.commit_group;");
}
template<int N_> __device__ __forceinline__ void cp_wait() {
    asm volatile("cp.async.wait_group %0;" :: "n"(N_));
}
__device__ __forceinline__ void ldsm_x4(uint32_t& r0, uint32_t& r1,
                                        uint32_t& r2, uint32_t& r3, uint32_t a) {
    asm volatile("ldmatrix.sync.aligned.m8n8.x4.shared.b16 {%0,%1,%2,%3}, [%4];"
                 : "=r"(r0), "=r"(r1), "=r"(r2), "=r"(r3) : "r"(a));
}

// single prepass: weights fp32->fp16 + qkv bias concat
__global__ void convert_weights_kernel(
    const float* __restrict__ qw, const float* __restrict__ kw,
    const float* __restrict__ vw, const float* __restrict__ pw,
    const float* __restrict__ f1, const float* __restrict__ f2,
    const float* __restrict__ qb, const float* __restrict__ kb,
    const float* __restrict__ vb,
    __half* __restrict__ wqkv, __half* __restrict__ wp,
    __half* __restrict__ wf1, __half* __restrict__ wf2,
    float* __restrict__ qkvbias) {
    const int CC = 262144, MC = 1048576;
    int gi = blockIdx.x * blockDim.x + threadIdx.x;
    if (gi < 1536) {
        float v = (gi < 512) ? qb[gi] : (gi < 1024 ? kb[gi - 512] : vb[gi - 1024]);
        qkvbias[gi] = v;
    }
    int i = gi * 4;
    const float* src; __half* dst; int off;
    if (i < CC)              { src = qw; dst = wqkv;          off = i; }
    else if (i < 2 * CC)     { src = kw; dst = wqkv + CC;     off = i - CC; }
    else if (i < 3 * CC)     { src = vw; dst = wqkv + 2 * CC; off = i - 2 * CC; }
    else if (i < 4 * CC)     { src = pw; dst = wp;            off = i - 3 * CC; }
    else if (i < 4 * CC + MC){ src = f1; dst = wf1;           off = i - 4 * CC; }
    else                     { src = f2; dst = wf2;           off = i - 4 * CC - MC; }
    float4 v = *(const float4*)(src + off);
    *(__half2*)(dst + off)     = __floats2half2_rn(v.x, v.y);
    *(__half2*)(dst + off + 2) = __floats2half2_rn(v.z, v.w);
}

// ============================ LN kernels (warp per row) ====================
__device__ __forceinline__ void warp_reduce_2(float& s, float& s2) {
    #pragma unroll
    for (int o = 16; o > 0; o >>= 1) {
        s  += __shfl_xor_sync(0xffffffffu, s,  o);
        s2 += __shfl_xor_sync(0xffffffffu, s2, o);
    }
}

__global__ __launch_bounds__(256)
void ln1_gather_kernel(const float* __restrict__ hid,
                       const float* __restrict__ g,
                       const float* __restrict__ b,
                       __half* __restrict__ xw) {
    int wr = blockIdx.x * 8 + (threadIdx.x >> 5);
    int lane = threadIdx.x & 31;
    int b_  = wr >> 12;
    int rem = wr & 4095;
    int wi  = rem >> 6;
    int n   = rem & 63;
    int wh = wi >> 3, ww = wi & 7;
    int i  = n  >> 3, j  = n  & 7;
    int sh_ = ((wh * 8 + i) + SSH) & 63;
    int sw_ = ((ww * 8 + j) + SSH) & 63;
    const float* src = hid + ((size_t)b_ * 4096 + sh_ * 64 + sw_) * CDIM;

    float4 v[4];
    float s = 0.f, s2 = 0.f;
    #pragma unroll
    for (int u = 0; u < 4; u++) {
        v[u] = *(const float4*)(src + lane * 4 + u * 128);
        s  += v[u].x + v[u].y + v[u].z + v[u].w;
        s2 += v[u].x * v[u].x + v[u].y * v[u].y + v[u].z * v[u].z + v[u].w * v[u].w;
    }
    warp_reduce_2(s, s2);
    float mu  = s * (1.f / CDIM);
    float var = s2 * (1.f / CDIM) - mu * mu;
    float inv = rsqrtf(var + 1e-5f);

    __half* dst = xw + (size_t)wr * CDIM;
    #pragma unroll
    for (int u = 0; u < 4; u++) {
        int c = lane * 4 + u * 128;
        float4 gg = *(const float4*)(g + c);
        float4 bb = *(const float4*)(b + c);
        __half2 h0 = __floats2half2_rn((v[u].x - mu) * inv * gg.x + bb.x,
                                       (v[u].y - mu) * inv * gg.y + bb.y);
        __half2 h1 = __floats2half2_rn((v[u].z - mu) * inv * gg.z + bb.z,
                                       (v[u].w - mu) * inv * gg.w + bb.w);
        *(__half2*)(dst + c)     = h0;
        *(__half2*)(dst + c + 2) = h1;
    }
}

__global__ __launch_bounds__(256)
void ln_plain_kernel(const float* __restrict__ x,
                     const float* __restrict__ g,
                     const float* __restrict__ b,
                     __half* __restrict__ y) {
    int r = blockIdx.x * 8 + (threadIdx.x >> 5);
    int lane = threadIdx.x & 31;
    const float* src = x + (size_t)r * CDIM;
    float4 v[4];
    float s = 0.f, s2 = 0.f;
    #pragma unroll
    for (int u = 0; u < 4; u++) {
        v[u] = *(const float4*)(src + lane * 4 + u * 128);
        s  += v[u].x + v[u].y + v[u].z + v[u].w;
        s2 += v[u].x * v[u].x + v[u].y * v[u].y + v[u].z * v[u].z + v[u].w * v[u].w;
    }
    warp_reduce_2(s, s2);
    float mu  = s * (1.f / CDIM);
    float var = s2 * (1.f / CDIM) - mu * mu;
    float inv = rsqrtf(var + 1e-5f);
    __half* dst = y + (size_t)r * CDIM;
    #pragma unroll
    for (int u = 0; u < 4; u++) {
        int c = lane * 4 + u * 128;
        float4 gg = *(const float4*)(g + c);
        float4 bb = *(const float4*)(b + c);
        __half2 h0 = __floats2half2_rn((v[u].x - mu) * inv * gg.x + bb.x,
                                       (v[u].y - mu) * inv * gg.y + bb.y);
        __half2 h1 = __floats2half2_rn((v[u].z - mu) * inv * gg.z + bb.z,
                                       (v[u].w - mu) * inv * gg.w + bb.w);
        *(__half2*)(dst + c)     = h0;
        *(__half2*)(dst + c + 2) = h1;
    }
}

// ============================ fp16 GEMM (R9 mainloop, frozen) ==============
// mode: 0 qkv head-major scatter (half), 1 gelu->half, 2 float+residual,
//       4 float+window-reverse-scatter+residual
__global__ __launch_bounds__(256, 2)
void gemm_f16_kernel(const __half* __restrict__ A, const __half* __restrict__ W,
                     const float* __restrict__ bias, void* __restrict__ Cout,
                     int N, int K, int mode, const float* __restrict__ add) {
    extern __shared__ char smem[];
    uint32_t sb = (uint32_t)__cvta_generic_to_shared(smem);

    const int tid  = threadIdx.x;
    const int warp = tid >> 5;
    const int lane = tid & 31;
    const int bm   = blockIdx.y * BM;
    const int bn   = blockIdx.x * BN;
    const int wm   = (warp & 3) * 32;
    const int wn   = (warp >> 2) * 64;
    const int lr   = lane >> 2;
    const int lc   = lane & 3;

    uint32_t aAddr[2], bAddr[4];
    {
        int arow = wm + (lane & 15);
        int akof = (lane >> 4) * 16;
        #pragma unroll
        for (int mt = 0; mt < 2; mt++)
            aAddr[mt] = sb + A_OFF + (uint32_t)((arow + mt * 16) * ROWB + akof);
        int brow = wn + (lane & 7) + ((lane >> 4) << 3);
        int bkof = ((lane >> 3) & 1) << 4;
        #pragma unroll
        for (int p = 0; p < 4; p++)
            bAddr[p] = sb + B_OFF + (uint32_t)((brow + p * 16) * ROWB + bkof);
    }

    float acc[2][8][4];
    #pragma unroll
    for (int mt = 0; mt < 2; mt++)
        #pragma unroll
        for (int nt = 0; nt < 8; nt++)
            #pragma unroll
            for (int r = 0; r < 4; r++) acc[mt][nt][r] = 0.f;

    const int KT = K / BK;

    auto load_tile = [&](int buf, int k0) {
        uint32_t sbase = sb + (uint32_t)(buf * STAGE_B);
        #pragma unroll
        for (int u = 0; u < 4; u++) {
            int ch = tid + u * 256;
            int row = ch >> 3, kq = ch & 7;
            cp_async16(sbase + A_OFF + (uint32_t)(row * ROWB + kq * 16),
                       A + (size_t)(bm + row) * K + k0 + kq * 8);
        }
        #pragma unroll
        for (int u = 0; u < 4; u++) {
            int ch = tid + u * 256;
            int row = ch >> 3, kq = ch & 7;
            cp_async16(sbase + B_OFF + (uint32_t)(row * ROWB + kq * 16),
                       W + (size_t)(bn + row) * K + k0 + kq * 8);
        }
        cp_commit();
    };

    load_tile(0, 0);

    for (int kt = 0; kt < KT; kt++) {
        int cur = kt & 1;
        if (kt + 1 < KT) {
            load_tile(cur ^ 1, (kt + 1) * BK);
            cp_wait<1>();
        } else {
            cp_wait<0>();
        }
        __syncthreads();

        uint32_t soff = (uint32_t)(cur * STAGE_B);
        #pragma unroll
        for (int ks = 0; ks < BK; ks += 16) {
            uint32_t af[2][4], bf[8][2];
            #pragma unroll
            for (int mt = 0; mt < 2; mt++)
                ldsm_x4(af[mt][0], af[mt][1], af[mt][2], af[mt][3],
                        aAddr[mt] + soff + ks * 2);
            #pragma unroll
            for (int p = 0; p < 4; p++)
                ldsm_x4(bf[2 * p][0], bf[2 * p][1], bf[2 * p + 1][0],
                        bf[2 * p + 1][1], bAddr[p] + soff + ks * 2);
            #pragma unroll
            for (int mt = 0; mt < 2; mt++)
                #pragma unroll
                for (int nt = 0; nt < 8; nt++) {
                    asm volatile(
                        "mma.sync.aligned.m16n8k16.row.col.f32.f16.f16.f32 "
                        "{%0,%1,%2,%3}, {%4,%5,%6,%7}, {%8,%9}, {%0,%1,%2,%3};\n"
                        : "+f"(acc[mt][nt][0]), "+f"(acc[mt][nt][1]),
                          "+f"(acc[mt][nt][2]), "+f"(acc[mt][nt][3])
                        : "r"(af[mt][0]), "r"(af[mt][1]), "r"(af[mt][2]), "r"(af[mt][3]),
                          "r"(bf[nt][0]), "r"(bf[nt][1]));
                }
        }
        __syncthreads();
    }

    // epilogue
    #pragma unroll
    for (int mt = 0; mt < 2; mt++) {
        #pragma unroll
        for (int h = 0; h < 2; h++) {
            int row = bm + wm + mt * 16 + lr + h * 8;
            size_t orow = (size_t)row;
            if (mode == 4) {
                int b_ = row >> 12, wi = (row >> 6) & 63, n = row & 63;
                int wh = wi >> 3, ww = wi & 7, i = n >> 3, j = n & 7;
                int sh_ = ((wh * 8 + i) + SSH) & 63;
                int sw_ = ((ww * 8 + j) + SSH) & 63;
                orow = (size_t)b_ * 4096 + sh_ * 64 + sw_;
            }
            #pragma unroll
            for (int nt = 0; nt < 8; nt++) {
                int col = bn + wn + nt * 8 + 2 * lc;
                float v0 = acc[mt][nt][2 * h + 0] + bias[col];
                float v1 = acc[mt][nt][2 * h + 1] + bias[col + 1];
                if (mode == 0) {
                    int which = col >> 9;
                    int hc = col & 511;
                    int head = hc >> 5, d = hc & 31;
                    size_t off = (size_t)which * TCH +
                        ((((size_t)(row >> 6) * NHEADS + head) * 64) +
                         (row & 63)) * 32 + d;
                    *(__half2*)((__half*)Cout + off) = __floats2half2_rn(v0, v1);
                } else if (mode == 1) {
                    v0 = 0.5f * v0 * (1.f + erff(v0 * 0.70710678118654752f));
                    v1 = 0.5f * v1 * (1.f + erff(v1 * 0.70710678118654752f));
                    __half* crow = (__half*)Cout + (size_t)row * N + col;
                    *(__half2*)crow = __floats2half2_rn(v0, v1);
                } else {
                    const float* ar = add + orow * N + col;
                    v0 += ar[0]; v1 += ar[1];
                    float* crow = (float*)Cout + orow * N + col;
                    crow[0] = v0; crow[1] = v1;
                }
            }
        }
    }
}

// ============================ attention ====================================
// one block per (window, head), 64 threads. Head-major qkv. Scores/probs in
// HALF smem (max/sum fp32) -> ~17.6 KB/block -> 12 blocks/SM.
__global__ __launch_bounds__(64, 12)
void attn_kernel(const __half* __restrict__ qkv, const float* __restrict__ btab,
                 __half* __restrict__ ctx) {
    __shared__ __half2 ks2[64][16];
    __shared__ __half2 vs2[64][16];
    __shared__ __half  sc[64][66];
    __shared__ float   sbias[225];
    __shared__ int     rid[64];

    int win  = blockIdx.x;
    int head = blockIdx.y;
    int n    = threadIdx.x;

    int wi = win & 63;
    int wh = wi >> 3, ww = wi & 7;
    int i  = n  >> 3, j  = n  & 7;

    int hs = wh * 8 + i, wc = ww * 8 + j;
    int rh = (hs < 56) ? 0 : ((hs < 60) ? 1 : 2);
    int rw = (wc < 56) ? 0 : ((wc < 60) ? 1 : 2);
    rid[n] = rh * 3 + rw;

    size_t hbase = (((size_t)win * NHEADS + head) * 64) * 32;  // halves
    const uint4* kp = (const uint4*)(qkv + TCH + hbase + (size_t)n * 32);
    const uint4* vp = (const uint4*)(qkv + 2 * TCH + hbase + (size_t)n * 32);
    #pragma unroll
    for (int u = 0; u < 4; u++) {
        ((uint4*)ks2[n])[u] = kp[u];
        ((uint4*)vs2[n])[u] = vp[u];
    }
    float qr[32];
    {
        const __half2* qp = (const __half2*)(qkv + hbase + (size_t)n * 32);
        #pragma unroll
        for (int u = 0; u < 16; u++) {
            float2 a = __half22float2(qp[u]);
            qr[2 * u] = a.x; qr[2 * u + 1] = a.y;
        }
    }
    for (int t = n; t < 225; t += 64) sbias[t] = btab[t * NHEADS + head];
    __syncthreads();

    const float scale = 0.17677669529663687f;
    int myrid = rid[n];

    // pass 1: scores -> registers are too many; compute score, track max,
    // store RAW score in half (scores are O(1-10), half is plenty)
    float mx = -1e30f;
    float sraw[2];  (void)sraw;
    for (int m = 0; m < 64; m++) {
        float acc = 0.f;
        #pragma unroll
        for (int d2 = 0; d2 < 16; d2++) {
            float2 kv = __half22float2(ks2[m][d2]);
            acc += qr[2 * d2] * kv.x + qr[2 * d2 + 1] * kv.y;
        }
        int hk = m >> 3, wk = m & 7;
        int bidx = (i - hk + 7) * 15 + (j - wk + 7);
        float bv = sbias[bidx];
        float msk = (rid[m] == myrid) ? 0.f : -100.f;
        float s = acc * scale + bv + msk;
        sc[n][m] = __float2half(s);
        mx = fmaxf(mx, s);
    }

    float sum = 0.f;
    for (int m = 0; m < 64; m++) {
        float e = __expf(__half2float(sc[n][m]) - mx);
        sc[n][m] = __float2half(e);
        sum += e;
    }
    float inv = 1.f / sum;
    __half* o = ctx + ((size_t)win * 64 + n) * CDIM + head * 32;

    #pragma unroll
    for (int half_ = 0; half_ < 2; half_++) {
        float accv[16];
        #pragma unroll
        for (int d = 0; d < 16; d++) accv[d] = 0.f;
        for (int m = 0; m < 64; m++) {
            float p = __half2float(sc[n][m]);
            #pragma unroll
            for (int d2 = 0; d2 < 8; d2++) {
                float2 vv = __half22float2(vs2[m][half_ * 8 + d2]);
                accv[2 * d2]     += p * vv.x;
                accv[2 * d2 + 1] += p * vv.y;
            }
        }
        #pragma unroll
        for (int d = 0; d < 16; d += 2)
            *(__half2*)(o + half_ * 16 + d) =
                __floats2half2_rn(accv[d] * inv, accv[d + 1] * inv);
    }
}

// ============================ launch =======================================
extern "C" void kernel_launch(void* const* d_in, const int* in_sizes, int n_in,
                              void* d_out, int out_size) {
    const float* hid    = (const float*)d_in[0];
    const float* q_w    = (const float*)d_in[1];
    const float* q_b    = (const float*)d_in[2];
    const float* k_w    = (const float*)d_in[3];
    const float* k_b    = (const float*)d_in[4];
    const float* v_w    = (const float*)d_in[5];
    const float* v_b    = (const float*)d_in[6];
    const float* proj_w = (const float*)d_in[7];
    const float* proj_b = (const float*)d_in[8];
    const float* relb   = (const float*)d_in[9];
    const float* ln1w   = (const float*)d_in[10];
    const float* ln1b   = (const float*)d_in[11];
    const float* ln2w   = (const float*)d_in[12];
    const float* ln2b   = (const float*)d_in[13];
    const float* fc1w   = (const float*)d_in[14];
    const float* fc1b   = (const float*)d_in[15];
    const float* fc2w   = (const float*)d_in[16];
    const float* fc2b   = (const float*)d_in[17];

    unsigned char* base = nullptr;
    cudaGetSymbolAddress((void**)&base, g_scratch);
    const size_t TC = (size_t)NTOK * CDIM;
    __half* xw   = (__half*)base;
    __half* qkvb = (__half*)(base + TC * 2);
    __half* cx   = (__half*)(base + TC * 8);
    float*  hb   = (float*)(base + TC * 10);
    __half* yb   = (__half*)(base + TC * 14);
    __half* mlp  = (__half*)(base + TC * 16);
    unsigned char* wbase = base + TC * 24;
    const size_t CC = (size_t)CDIM * CDIM, MC = (size_t)MLPD * CDIM;
    __half* wqkv = (__half*)wbase;
    __half* wp   = wqkv + 3 * CC;
    __half* wf1  = wp + CC;
    __half* wf2  = wf1 + MC;
    float*  qkvbias = (float*)(wf2 + MC);

    float* out = (float*)d_out;

    cudaFuncSetAttribute(gemm_f16_kernel,
                         cudaFuncAttributeMaxDynamicSharedMemorySize, GEMM_SMEM);

    convert_weights_kernel<<<3072, 256>>>(q_w, k_w, v_w, proj_w, fc1w, fc2w,
                                          q_b, k_b, v_b,
                                          wqkv, wp, wf1, wf2, qkvbias);

    ln1_gather_kernel<<<NTOK / 8, 256>>>(hid, ln1w, ln1b, xw);

    gemm_f16_kernel<<<dim3(QKVN / BN, NTOK / BM), 256, GEMM_SMEM>>>(
        xw, wqkv, qkvbias, qkvb, QKVN, CDIM, 0, nullptr);

    attn_kernel<<<dim3(1024, NHEADS), 64>>>(qkvb, relb, cx);

    gemm_f16_kernel<<<dim3(CDIM / BN, NTOK / BM), 256, GEMM_SMEM>>>(
        cx, wp, proj_b, hb, CDIM, CDIM, 4, hid);

    ln_plain_kernel<<<NTOK / 8, 256>>>(hb, ln2w, ln2b, yb);

    gemm_f16_kernel<<<dim3(MLPD / BN, NTOK / BM), 256, GEMM_SMEM>>>(
        yb, wf1, fc1b, mlp, MLPD, CDIM, 1, nullptr);

    gemm_f16_kernel<<<dim3(CDIM / BN, NTOK / BM), 256, GEMM_SMEM>>>(
        mlp, wf2, fc2b, out, CDIM, MLPD, 2, hb);
}

// round 13
// speedup vs baseline: 1.0055x; 1.0055x over previous
#include <cuda_runtime.h>
#include <cuda_fp16.h>
#include <math.h>
#include <stdint.h>

// ---------------------------------------------------------------------------
// DonutSwinLayer: B=16, H=W=64, C=512, NH=16, HD=32, WS=8, N=64, SS=4, MLP=2048
// Round 13: attention with fp32 K/V smem tiles (no per-key cvt, LDS.128 loads).
//           GEMMs / LNs / prepass identical to R12.
// ---------------------------------------------------------------------------

#define NTOK   65536
#define CDIM   512
#define NHEADS 16
#define HDIM   32
#define SSH    4
#define MLPD   2048
#define QKVN   1536
#define TCH    33554432ULL          // NTOK*CDIM (halves per q/k/v plane)

#define BM 128
#define BN 128
#define BK 64
#define ROWB 144                    // bytes per smem row (72 halves, LDSM-safe)
#define A_OFF 0
#define B_OFF (BM * ROWB)           // 18432
#define STAGE_B ((BM + BN) * ROWB)  // 36864
#define NSTAGE 2
#define GEMM_SMEM (NSTAGE * STAGE_B)   // 73728

__device__ unsigned char g_scratch[(size_t)26 * NTOK * CDIM + (1u << 24)];

// ============================ helpers ======================================
__device__ __forceinline__ void cp_async16(uint32_t s, const void* g) {
    asm volatile("cp.async.cg.shared.global [%0], [%1], 16;" :: "r"(s), "l"(g));
}
__device__ __forceinline__ void cp_commit() {
    asm volatile("cp.async.commit_group;");
}
template<int N_> __device__ __forceinline__ void cp_wait() {
    asm volatile("cp.async.wait_group %0;" :: "n"(N_));
}
__device__ __forceinline__ void ldsm_x4(uint32_t& r0, uint32_t& r1,
                                        uint32_t& r2, uint32_t& r3, uint32_t a) {
    asm volatile("ldmatrix.sync.aligned.m8n8.x4.shared.b16 {%0,%1,%2,%3}, [%4];"
                 : "=r"(r0), "=r"(r1), "=r"(r2), "=r"(r3) : "r"(a));
}

// single prepass: weights fp32->fp16 + qkv bias concat
__global__ void convert_weights_kernel(
    const float* __restrict__ qw, const float* __restrict__ kw,
    const float* __restrict__ vw, const float* __restrict__ pw,
    const float* __restrict__ f1, const float* __restrict__ f2,
    const float* __restrict__ qb, const float* __restrict__ kb,
    const float* __restrict__ vb,
    __half* __restrict__ wqkv, __half* __restrict__ wp,
    __half* __restrict__ wf1, __half* __restrict__ wf2,
    float* __restrict__ qkvbias) {
    const int CC = 262144, MC = 1048576;
    int gi = blockIdx.x * blockDim.x + threadIdx.x;
    if (gi < 1536) {
        float v = (gi < 512) ? qb[gi] : (gi < 1024 ? kb[gi - 512] : vb[gi - 1024]);
        qkvbias[gi] = v;
    }
    int i = gi * 4;
    const float* src; __half* dst; int off;
    if (i < CC)              { src = qw; dst = wqkv;          off = i; }
    else if (i < 2 * CC)     { src = kw; dst = wqkv + CC;     off = i - CC; }
    else if (i < 3 * CC)     { src = vw; dst = wqkv + 2 * CC; off = i - 2 * CC; }
    else if (i < 4 * CC)     { src = pw; dst = wp;            off = i - 3 * CC; }
    else if (i < 4 * CC + MC){ src = f1; dst = wf1;           off = i - 4 * CC; }
    else                     { src = f2; dst = wf2;           off = i - 4 * CC - MC; }
    float4 v = *(const float4*)(src + off);
    *(__half2*)(dst + off)     = __floats2half2_rn(v.x, v.y);
    *(__half2*)(dst + off + 2) = __floats2half2_rn(v.z, v.w);
}

// ============================ LN kernels (warp per row) ====================
__device__ __forceinline__ void warp_reduce_2(float& s, float& s2) {
    #pragma unroll
    for (int o = 16; o > 0; o >>= 1) {
        s  += __shfl_xor_sync(0xffffffffu, s,  o);
        s2 += __shfl_xor_sync(0xffffffffu, s2, o);
    }
}

__global__ __launch_bounds__(256)
void ln1_gather_kernel(const float* __restrict__ hid,
                       const float* __restrict__ g,
                       const float* __restrict__ b,
                       __half* __restrict__ xw) {
    int wr = blockIdx.x * 8 + (threadIdx.x >> 5);
    int lane = threadIdx.x & 31;
    int b_  = wr >> 12;
    int rem = wr & 4095;
    int wi  = rem >> 6;
    int n   = rem & 63;
    int wh = wi >> 3, ww = wi & 7;
    int i  = n  >> 3, j  = n  & 7;
    int sh_ = ((wh * 8 + i) + SSH) & 63;
    int sw_ = ((ww * 8 + j) + SSH) & 63;
    const float* src = hid + ((size_t)b_ * 4096 + sh_ * 64 + sw_) * CDIM;

    float4 v[4];
    float s = 0.f, s2 = 0.f;
    #pragma unroll
    for (int u = 0; u < 4; u++) {
        v[u] = *(const float4*)(src + lane * 4 + u * 128);
        s  += v[u].x + v[u].y + v[u].z + v[u].w;
        s2 += v[u].x * v[u].x + v[u].y * v[u].y + v[u].z * v[u].z + v[u].w * v[u].w;
    }
    warp_reduce_2(s, s2);
    float mu  = s * (1.f / CDIM);
    float var = s2 * (1.f / CDIM) - mu * mu;
    float inv = rsqrtf(var + 1e-5f);

    __half* dst = xw + (size_t)wr * CDIM;
    #pragma unroll
    for (int u = 0; u < 4; u++) {
        int c = lane * 4 + u * 128;
        float4 gg = *(const float4*)(g + c);
        float4 bb = *(const float4*)(b + c);
        __half2 h0 = __floats2half2_rn((v[u].x - mu) * inv * gg.x + bb.x,
                                       (v[u].y - mu) * inv * gg.y + bb.y);
        __half2 h1 = __floats2half2_rn((v[u].z - mu) * inv * gg.z + bb.z,
                                       (v[u].w - mu) * inv * gg.w + bb.w);
        *(__half2*)(dst + c)     = h0;
        *(__half2*)(dst + c + 2) = h1;
    }
}

__global__ __launch_bounds__(256)
void ln_plain_kernel(const float* __restrict__ x,
                     const float* __restrict__ g,
                     const float* __restrict__ b,
                     __half* __restrict__ y) {
    int r = blockIdx.x * 8 + (threadIdx.x >> 5);
    int lane = threadIdx.x & 31;
    const float* src = x + (size_t)r * CDIM;
    float4 v[4];
    float s = 0.f, s2 = 0.f;
    #pragma unroll
    for (int u = 0; u < 4; u++) {
        v[u] = *(const float4*)(src + lane * 4 + u * 128);
        s  += v[u].x + v[u].y + v[u].z + v[u].w;
        s2 += v[u].x * v[u].x + v[u].y * v[u].y + v[u].z * v[u].z + v[u].w * v[u].w;
    }
    warp_reduce_2(s, s2);
    float mu  = s * (1.f / CDIM);
    float var = s2 * (1.f / CDIM) - mu * mu;
    float inv = rsqrtf(var + 1e-5f);
    __half* dst = y + (size_t)r * CDIM;
    #pragma unroll
    for (int u = 0; u < 4; u++) {
        int c = lane * 4 + u * 128;
        float4 gg = *(const float4*)(g + c);
        float4 bb = *(const float4*)(b + c);
        __half2 h0 = __floats2half2_rn((v[u].x - mu) * inv * gg.x + bb.x,
                                       (v[u].y - mu) * inv * gg.y + bb.y);
        __half2 h1 = __floats2half2_rn((v[u].z - mu) * inv * gg.z + bb.z,
                                       (v[u].w - mu) * inv * gg.w + bb.w);
        *(__half2*)(dst + c)     = h0;
        *(__half2*)(dst + c + 2) = h1;
    }
}

// ============================ fp16 GEMM (frozen) ===========================
// mode: 0 qkv head-major scatter (half), 1 gelu->half, 2 float+residual,
//       4 float+window-reverse-scatter+residual
__global__ __launch_bounds__(256, 2)
void gemm_f16_kernel(const __half* __restrict__ A, const __half* __restrict__ W,
                     const float* __restrict__ bias, void* __restrict__ Cout,
                     int N, int K, int mode, const float* __restrict__ add) {
    extern __shared__ char smem[];
    uint32_t sb = (uint32_t)__cvta_generic_to_shared(smem);

    const int tid  = threadIdx.x;
    const int warp = tid >> 5;
    const int lane = tid & 31;
    const int bm   = blockIdx.y * BM;
    const int bn   = blockIdx.x * BN;
    const int wm   = (warp & 3) * 32;
    const int wn   = (warp >> 2) * 64;
    const int lr   = lane >> 2;
    const int lc   = lane & 3;

    uint32_t aAddr[2], bAddr[4];
    {
        int arow = wm + (lane & 15);
        int akof = (lane >> 4) * 16;
        #pragma unroll
        for (int mt = 0; mt < 2; mt++)
            aAddr[mt] = sb + A_OFF + (uint32_t)((arow + mt * 16) * ROWB + akof);
        int brow = wn + (lane & 7) + ((lane >> 4) << 3);
        int bkof = ((lane >> 3) & 1) << 4;
        #pragma unroll
        for (int p = 0; p < 4; p++)
            bAddr[p] = sb + B_OFF + (uint32_t)((brow + p * 16) * ROWB + bkof);
    }

    float acc[2][8][4];
    #pragma unroll
    for (int mt = 0; mt < 2; mt++)
        #pragma unroll
        for (int nt = 0; nt < 8; nt++)
            #pragma unroll
            for (int r = 0; r < 4; r++) acc[mt][nt][r] = 0.f;

    const int KT = K / BK;

    auto load_tile = [&](int buf, int k0) {
        uint32_t sbase = sb + (uint32_t)(buf * STAGE_B);
        #pragma unroll
        for (int u = 0; u < 4; u++) {
            int ch = tid + u * 256;
            int row = ch >> 3, kq = ch & 7;
            cp_async16(sbase + A_OFF + (uint32_t)(row * ROWB + kq * 16),
                       A + (size_t)(bm + row) * K + k0 + kq * 8);
        }
        #pragma unroll
        for (int u = 0; u < 4; u++) {
            int ch = tid + u * 256;
            int row = ch >> 3, kq = ch & 7;
            cp_async16(sbase + B_OFF + (uint32_t)(row * ROWB + kq * 16),
                       W + (size_t)(bn + row) * K + k0 + kq * 8);
        }
        cp_commit();
    };

    load_tile(0, 0);

    for (int kt = 0; kt < KT; kt++) {
        int cur = kt & 1;
        if (kt + 1 < KT) {
            load_tile(cur ^ 1, (kt + 1) * BK);
            cp_wait<1>();
        } else {
            cp_wait<0>();
        }
        __syncthreads();

        uint32_t soff = (uint32_t)(cur * STAGE_B);
        #pragma unroll
        for (int ks = 0; ks < BK; ks += 16) {
            uint32_t af[2][4], bf[8][2];
            #pragma unroll
            for (int mt = 0; mt < 2; mt++)
                ldsm_x4(af[mt][0], af[mt][1], af[mt][2], af[mt][3],
                        aAddr[mt] + soff + ks * 2);
            #pragma unroll
            for (int p = 0; p < 4; p++)
                ldsm_x4(bf[2 * p][0], bf[2 * p][1], bf[2 * p + 1][0],
                        bf[2 * p + 1][1], bAddr[p] + soff + ks * 2);
            #pragma unroll
            for (int mt = 0; mt < 2; mt++)
                #pragma unroll
                for (int nt = 0; nt < 8; nt++) {
                    asm volatile(
                        "mma.sync.aligned.m16n8k16.row.col.f32.f16.f16.f32 "
                        "{%0,%1,%2,%3}, {%4,%5,%6,%7}, {%8,%9}, {%0,%1,%2,%3};\n"
                        : "+f"(acc[mt][nt][0]), "+f"(acc[mt][nt][1]),
                          "+f"(acc[mt][nt][2]), "+f"(acc[mt][nt][3])
                        : "r"(af[mt][0]), "r"(af[mt][1]), "r"(af[mt][2]), "r"(af[mt][3]),
                          "r"(bf[nt][0]), "r"(bf[nt][1]));
                }
        }
        __syncthreads();
    }

    // epilogue
    #pragma unroll
    for (int mt = 0; mt < 2; mt++) {
        #pragma unroll
        for (int h = 0; h < 2; h++) {
            int row = bm + wm + mt * 16 + lr + h * 8;
            size_t orow = (size_t)row;
            if (mode == 4) {
                int b_ = row >> 12, wi = (row >> 6) & 63, n = row & 63;
                int wh = wi >> 3, ww = wi & 7, i = n >> 3, j = n & 7;
                int sh_ = ((wh * 8 + i) + SSH) & 63;
                int sw_ = ((ww * 8 + j) + SSH) & 63;
                orow = (size_t)b_ * 4096 + sh_ * 64 + sw_;
            }
            #pragma unroll
            for (int nt = 0; nt < 8; nt++) {
                int col = bn + wn + nt * 8 + 2 * lc;
                float v0 = acc[mt][nt][2 * h + 0] + bias[col];
                float v1 = acc[mt][nt][2 * h + 1] + bias[col + 1];
                if (mode == 0) {
                    int which = col >> 9;
                    int hc = col & 511;
                    int head = hc >> 5, d = hc & 31;
                    size_t off = (size_t)which * TCH +
                        ((((size_t)(row >> 6) * NHEADS + head) * 64) +
                         (row & 63)) * 32 + d;
                    *(__half2*)((__half*)Cout + off) = __floats2half2_rn(v0, v1);
                } else if (mode == 1) {
                    v0 = 0.5f * v0 * (1.f + erff(v0 * 0.70710678118654752f));
                    v1 = 0.5f * v1 * (1.f + erff(v1 * 0.70710678118654752f));
                    __half* crow = (__half*)Cout + (size_t)row * N + col;
                    *(__half2*)crow = __floats2half2_rn(v0, v1);
                } else {
                    const float* ar = add + orow * N + col;
                    v0 += ar[0]; v1 += ar[1];
                    float* crow = (float*)Cout + orow * N + col;
                    crow[0] = v0; crow[1] = v1;
                }
            }
        }
    }
}

// ============================ attention ====================================
// one block per (window, head), 64 threads. Head-major qkv. K/V converted to
// fp32 smem tiles at fill (padded rows, stride 36 floats). Inner loops are
// pure LDS.128 + FFMA (no per-key cvt). Probs in half smem.
__global__ __launch_bounds__(64, 8)
void attn_kernel(const __half* __restrict__ qkv, const float* __restrict__ btab,
                 __half* __restrict__ ctx) {
    __shared__ float  ksf[64][36];
    __shared__ float  vsf[64][36];
    __shared__ __half sc[64][66];
    __shared__ float  sbias[225];
    __shared__ int    rid[64];

    int win  = blockIdx.x;
    int head = blockIdx.y;
    int n    = threadIdx.x;

    int wi = win & 63;
    int wh = wi >> 3, ww = wi & 7;
    int i  = n  >> 3, j  = n  & 7;

    int hs = wh * 8 + i, wc = ww * 8 + j;
    int rh = (hs < 56) ? 0 : ((hs < 60) ? 1 : 2);
    int rw = (wc < 56) ? 0 : ((wc < 60) ? 1 : 2);
    rid[n] = rh * 3 + rw;

    size_t hbase = (((size_t)win * NHEADS + head) * 64) * 32;  // halves
    // fill K/V as fp32 (thread n owns row n)
    {
        const __half2* kp = (const __half2*)(qkv + TCH + hbase + (size_t)n * 32);
        const __half2* vp = (const __half2*)(qkv + 2 * TCH + hbase + (size_t)n * 32);
        #pragma unroll
        for (int u = 0; u < 16; u++) {
            float2 kk = __half22float2(kp[u]);
            float2 vv = __half22float2(vp[u]);
            ksf[n][2 * u] = kk.x; ksf[n][2 * u + 1] = kk.y;
            vsf[n][2 * u] = vv.x; vsf[n][2 * u + 1] = vv.y;
        }
    }
    float qr[32];
    {
        const __half2* qp = (const __half2*)(qkv + hbase + (size_t)n * 32);
        #pragma unroll
        for (int u = 0; u < 16; u++) {
            float2 a = __half22float2(qp[u]);
            qr[2 * u] = a.x; qr[2 * u + 1] = a.y;
        }
    }
    for (int t = n; t < 225; t += 64) sbias[t] = btab[t * NHEADS + head];
    __syncthreads();

    const float scale = 0.17677669529663687f;
    int myrid = rid[n];

    float mx = -1e30f;
    for (int m = 0; m < 64; m++) {
        float4 k0 = *(const float4*)&ksf[m][0];
        float4 k1 = *(const float4*)&ksf[m][4];
        float4 k2 = *(const float4*)&ksf[m][8];
        float4 k3 = *(const float4*)&ksf[m][12];
        float4 k4 = *(const float4*)&ksf[m][16];
        float4 k5 = *(const float4*)&ksf[m][20];
        float4 k6 = *(const float4*)&ksf[m][24];
        float4 k7 = *(const float4*)&ksf[m][28];
        float acc =
            qr[0]*k0.x + qr[1]*k0.y + qr[2]*k0.z + qr[3]*k0.w +
            qr[4]*k1.x + qr[5]*k1.y + qr[6]*k1.z + qr[7]*k1.w +
            qr[8]*k2.x + qr[9]*k2.y + qr[10]*k2.z + qr[11]*k2.w +
            qr[12]*k3.x + qr[13]*k3.y + qr[14]*k3.z + qr[15]*k3.w +
            qr[16]*k4.x + qr[17]*k4.y + qr[18]*k4.z + qr[19]*k4.w +
            qr[20]*k5.x + qr[21]*k5.y + qr[22]*k5.z + qr[23]*k5.w +
            qr[24]*k6.x + qr[25]*k6.y + qr[26]*k6.z + qr[27]*k6.w +
            qr[28]*k7.x + qr[29]*k7.y + qr[30]*k7.z + qr[31]*k7.w;
        int hk = m >> 3, wk = m & 7;
        int bidx = (i - hk + 7) * 15 + (j - wk + 7);
        float bv = sbias[bidx];
        float msk = (rid[m] == myrid) ? 0.f : -100.f;
        float s = acc * scale + bv + msk;
        sc[n][m] = __float2half(s);
        mx = fmaxf(mx, s);
    }

    float sum = 0.f;
    for (int m = 0; m < 64; m++) {
        float e = __expf(__half2float(sc[n][m]) - mx);
        sc[n][m] = __float2half(e);
        sum += e;
    }
    float inv = 1.f / sum;

    float accv[32];
    #pragma unroll
    for (int d = 0; d < 32; d++) accv[d] = 0.f;
    for (int m = 0; m < 64; m++) {
        float p = __half2float(sc[n][m]);
        #pragma unroll
        for (int dq = 0; dq < 8; dq++) {
            float4 vv = *(const float4*)&vsf[m][dq * 4];
            accv[4 * dq + 0] += p * vv.x;
            accv[4 * dq + 1] += p * vv.y;
            accv[4 * dq + 2] += p * vv.z;
            accv[4 * dq + 3] += p * vv.w;
        }
    }
    __half* o = ctx + ((size_t)win * 64 + n) * CDIM + head * 32;
    #pragma unroll
    for (int d = 0; d < 32; d += 2)
        *(__half2*)(o + d) = __floats2half2_rn(accv[d] * inv, accv[d + 1] * inv);
}

// ============================ launch =======================================
extern "C" void kernel_launch(void* const* d_in, const int* in_sizes, int n_in,
                              void* d_out, int out_size) {
    const float* hid    = (const float*)d_in[0];
    const float* q_w    = (const float*)d_in[1];
    const float* q_b    = (const float*)d_in[2];
    const float* k_w    = (const float*)d_in[3];
    const float* k_b    = (const float*)d_in[4];
    const float* v_w    = (const float*)d_in[5];
    const float* v_b    = (const float*)d_in[6];
    const float* proj_w = (const float*)d_in[7];
    const float* proj_b = (const float*)d_in[8];
    const float* relb   = (const float*)d_in[9];
    const float* ln1w   = (const float*)d_in[10];
    const float* ln1b   = (const float*)d_in[11];
    const float* ln2w   = (const float*)d_in[12];
    const float* ln2b   = (const float*)d_in[13];
    const float* fc1w   = (const float*)d_in[14];
    const float* fc1b   = (const float*)d_in[15];
    const float* fc2w   = (const float*)d_in[16];
    const float* fc2b   = (const float*)d_in[17];

    unsigned char* base = nullptr;
    cudaGetSymbolAddress((void**)&base, g_scratch);
    const size_t TC = (size_t)NTOK * CDIM;
    __half* xw   = (__half*)base;
    __half* qkvb = (__half*)(base + TC * 2);
    __half* cx   = (__half*)(base + TC * 8);
    float*  hb   = (float*)(base + TC * 10);
    __half* yb   = (__half*)(base + TC * 14);
    __half* mlp  = (__half*)(base + TC * 16);
    unsigned char* wbase = base + TC * 24;
    const size_t CC = (size_t)CDIM * CDIM, MC = (size_t)MLPD * CDIM;
    __half* wqkv = (__half*)wbase;
    __half* wp   = wqkv + 3 * CC;
    __half* wf1  = wp + CC;
    __half* wf2  = wf1 + MC;
    float*  qkvbias = (float*)(wf2 + MC);

    float* out = (float*)d_out;

    cudaFuncSetAttribute(gemm_f16_kernel,
                         cudaFuncAttributeMaxDynamicSharedMemorySize, GEMM_SMEM);

    convert_weights_kernel<<<3072, 256>>>(q_w, k_w, v_w, proj_w, fc1w, fc2w,
                                          q_b, k_b, v_b,
                                          wqkv, wp, wf1, wf2, qkvbias);

    ln1_gather_kernel<<<NTOK / 8, 256>>>(hid, ln1w, ln1b, xw);

    gemm_f16_kernel<<<dim3(QKVN / BN, NTOK / BM), 256, GEMM_SMEM>>>(
        xw, wqkv, qkvbias, qkvb, QKVN, CDIM, 0, nullptr);

    attn_kernel<<<dim3(1024, NHEADS), 64>>>(qkvb, relb, cx);

    gemm_f16_kernel<<<dim3(CDIM / BN, NTOK / BM), 256, GEMM_SMEM>>>(
        cx, wp, proj_b, hb, CDIM, CDIM, 4, hid);

    ln_plain_kernel<<<NTOK / 8, 256>>>(hb, ln2w, ln2b, yb);

    gemm_f16_kernel<<<dim3(MLPD / BN, NTOK / BM), 256, GEMM_SMEM>>>(
        yb, wf1, fc1b, mlp, MLPD, CDIM, 1, nullptr);

    gemm_f16_kernel<<<dim3(CDIM / BN, NTOK / BM), 256, GEMM_SMEM>>>(
        mlp, wf2, fc2b, out, CDIM, MLPD, 2, hb);
}

// round 14
// speedup vs baseline: 1.0742x; 1.0683x over previous
#include <cuda_runtime.h>
#include <cuda_fp16.h>
#include <math.h>
#include <stdint.h>

// ---------------------------------------------------------------------------
// DonutSwinLayer: B=16, H=W=64, C=512, NH=16, HD=32, WS=8, N=64, SS=4, MLP=2048
// Round 14: attention in half2/HFMA2 (half the LDS, no cvt), 12 blocks/SM.
//           GEMMs / LNs / prepass identical to R13.
// ---------------------------------------------------------------------------

#define NTOK   65536
#define CDIM   512
#define NHEADS 16
#define HDIM   32
#define SSH    4
#define MLPD   2048
#define QKVN   1536
#define TCH    33554432ULL          // NTOK*CDIM (halves per q/k/v plane)

#define BM 128
#define BN 128
#define BK 64
#define ROWB 144                    // bytes per smem row (72 halves, LDSM-safe)
#define A_OFF 0
#define B_OFF (BM * ROWB)           // 18432
#define STAGE_B ((BM + BN) * ROWB)  // 36864
#define NSTAGE 2
#define GEMM_SMEM (NSTAGE * STAGE_B)   // 73728

__device__ unsigned char g_scratch[(size_t)26 * NTOK * CDIM + (1u << 24)];

// ============================ helpers ======================================
__device__ __forceinline__ void cp_async16(uint32_t s, const void* g) {
    asm volatile("cp.async.cg.shared.global [%0], [%1], 16;" :: "r"(s), "l"(g));
}
__device__ __forceinline__ void cp_commit() {
    asm volatile("cp.async.commit_group;");
}
template<int N_> __device__ __forceinline__ void cp_wait() {
    asm volatile("cp.async.wait_group %0;" :: "n"(N_));
}
__device__ __forceinline__ void ldsm_x4(uint32_t& r0, uint32_t& r1,
                                        uint32_t& r2, uint32_t& r3, uint32_t a) {
    asm volatile("ldmatrix.sync.aligned.m8n8.x4.shared.b16 {%0,%1,%2,%3}, [%4];"
                 : "=r"(r0), "=r"(r1), "=r"(r2), "=r"(r3) : "r"(a));
}

// single prepass: weights fp32->fp16 + qkv bias concat
__global__ void convert_weights_kernel(
    const float* __restrict__ qw, const float* __restrict__ kw,
    const float* __restrict__ vw, const float* __restrict__ pw,
    const float* __restrict__ f1, const float* __restrict__ f2,
    const float* __restrict__ qb, const float* __restrict__ kb,
    const float* __restrict__ vb,
    __half* __restrict__ wqkv, __half* __restrict__ wp,
    __half* __restrict__ wf1, __half* __restrict__ wf2,
    float* __restrict__ qkvbias) {
    const int CC = 262144, MC = 1048576;
    int gi = blockIdx.x * blockDim.x + threadIdx.x;
    if (gi < 1536) {
        float v = (gi < 512) ? qb[gi] : (gi < 1024 ? kb[gi - 512] : vb[gi - 1024]);
        qkvbias[gi] = v;
    }
    int i = gi * 4;
    const float* src; __half* dst; int off;
    if (i < CC)              { src = qw; dst = wqkv;          off = i; }
    else if (i < 2 * CC)     { src = kw; dst = wqkv + CC;     off = i - CC; }
    else if (i < 3 * CC)     { src = vw; dst = wqkv + 2 * CC; off = i - 2 * CC; }
    else if (i < 4 * CC)     { src = pw; dst = wp;            off = i - 3 * CC; }
    else if (i < 4 * CC + MC){ src = f1; dst = wf1;           off = i - 4 * CC; }
    else                     { src = f2; dst = wf2;           off = i - 4 * CC - MC; }
    float4 v = *(const float4*)(src + off);
    *(__half2*)(dst + off)     = __floats2half2_rn(v.x, v.y);
    *(__half2*)(dst + off + 2) = __floats2half2_rn(v.z, v.w);
}

// ============================ LN kernels (warp per row) ====================
__device__ __forceinline__ void warp_reduce_2(float& s, float& s2) {
    #pragma unroll
    for (int o = 16; o > 0; o >>= 1) {
        s  += __shfl_xor_sync(0xffffffffu, s,  o);
        s2 += __shfl_xor_sync(0xffffffffu, s2, o);
    }
}

__global__ __launch_bounds__(256)
void ln1_gather_kernel(const float* __restrict__ hid,
                       const float* __restrict__ g,
                       const float* __restrict__ b,
                       __half* __restrict__ xw) {
    int wr = blockIdx.x * 8 + (threadIdx.x >> 5);
    int lane = threadIdx.x & 31;
    int b_  = wr >> 12;
    int rem = wr & 4095;
    int wi  = rem >> 6;
    int n   = rem & 63;
    int wh = wi >> 3, ww = wi & 7;
    int i  = n  >> 3, j  = n  & 7;
    int sh_ = ((wh * 8 + i) + SSH) & 63;
    int sw_ = ((ww * 8 + j) + SSH) & 63;
    const float* src = hid + ((size_t)b_ * 4096 + sh_ * 64 + sw_) * CDIM;

    float4 v[4];
    float s = 0.f, s2 = 0.f;
    #pragma unroll
    for (int u = 0; u < 4; u++) {
        v[u] = *(const float4*)(src + lane * 4 + u * 128);
        s  += v[u].x + v[u].y + v[u].z + v[u].w;
        s2 += v[u].x * v[u].x + v[u].y * v[u].y + v[u].z * v[u].z + v[u].w * v[u].w;
    }
    warp_reduce_2(s, s2);
    float mu  = s * (1.f / CDIM);
    float var = s2 * (1.f / CDIM) - mu * mu;
    float inv = rsqrtf(var + 1e-5f);

    __half* dst = xw + (size_t)wr * CDIM;
    #pragma unroll
    for (int u = 0; u < 4; u++) {
        int c = lane * 4 + u * 128;
        float4 gg = *(const float4*)(g + c);
        float4 bb = *(const float4*)(b + c);
        __half2 h0 = __floats2half2_rn((v[u].x - mu) * inv * gg.x + bb.x,
                                       (v[u].y - mu) * inv * gg.y + bb.y);
        __half2 h1 = __floats2half2_rn((v[u].z - mu) * inv * gg.z + bb.z,
                                       (v[u].w - mu) * inv * gg.w + bb.w);
        *(__half2*)(dst + c)     = h0;
        *(__half2*)(dst + c + 2) = h1;
    }
}

__global__ __launch_bounds__(256)
void ln_plain_kernel(const float* __restrict__ x,
                     const float* __restrict__ g,
                     const float* __restrict__ b,
                     __half* __restrict__ y) {
    int r = blockIdx.x * 8 + (threadIdx.x >> 5);
    int lane = threadIdx.x & 31;
    const float* src = x + (size_t)r * CDIM;
    float4 v[4];
    float s = 0.f, s2 = 0.f;
    #pragma unroll
    for (int u = 0; u < 4; u++) {
        v[u] = *(const float4*)(src + lane * 4 + u * 128);
        s  += v[u].x + v[u].y + v[u].z + v[u].w;
        s2 += v[u].x * v[u].x + v[u].y * v[u].y + v[u].z * v[u].z + v[u].w * v[u].w;
    }
    warp_reduce_2(s, s2);
    float mu  = s * (1.f / CDIM);
    float var = s2 * (1.f / CDIM) - mu * mu;
    float inv = rsqrtf(var + 1e-5f);
    __half* dst = y + (size_t)r * CDIM;
    #pragma unroll
    for (int u = 0; u < 4; u++) {
        int c = lane * 4 + u * 128;
        float4 gg = *(const float4*)(g + c);
        float4 bb = *(const float4*)(b + c);
        __half2 h0 = __floats2half2_rn((v[u].x - mu) * inv * gg.x + bb.x,
                                       (v[u].y - mu) * inv * gg.y + bb.y);
        __half2 h1 = __floats2half2_rn((v[u].z - mu) * inv * gg.z + bb.z,
                                       (v[u].w - mu) * inv * gg.w + bb.w);
        *(__half2*)(dst + c)     = h0;
        *(__half2*)(dst + c + 2) = h1;
    }
}

// ============================ fp16 GEMM (frozen) ===========================
// mode: 0 qkv head-major scatter (half), 1 gelu->half, 2 float+residual,
//       4 float+window-reverse-scatter+residual
__global__ __launch_bounds__(256, 2)
void gemm_f16_kernel(const __half* __restrict__ A, const __half* __restrict__ W,
                     const float* __restrict__ bias, void* __restrict__ Cout,
                     int N, int K, int mode, const float* __restrict__ add) {
    extern __shared__ char smem[];
    uint32_t sb = (uint32_t)__cvta_generic_to_shared(smem);

    const int tid  = threadIdx.x;
    const int warp = tid >> 5;
    const int lane = tid & 31;
    const int bm   = blockIdx.y * BM;
    const int bn   = blockIdx.x * BN;
    const int wm   = (warp & 3) * 32;
    const int wn   = (warp >> 2) * 64;
    const int lr   = lane >> 2;
    const int lc   = lane & 3;

    uint32_t aAddr[2], bAddr[4];
    {
        int arow = wm + (lane & 15);
        int akof = (lane >> 4) * 16;
        #pragma unroll
        for (int mt = 0; mt < 2; mt++)
            aAddr[mt] = sb + A_OFF + (uint32_t)((arow + mt * 16) * ROWB + akof);
        int brow = wn + (lane & 7) + ((lane >> 4) << 3);
        int bkof = ((lane >> 3) & 1) << 4;
        #pragma unroll
        for (int p = 0; p < 4; p++)
            bAddr[p] = sb + B_OFF + (uint32_t)((brow + p * 16) * ROWB + bkof);
    }

    float acc[2][8][4];
    #pragma unroll
    for (int mt = 0; mt < 2; mt++)
        #pragma unroll
        for (int nt = 0; nt < 8; nt++)
            #pragma unroll
            for (int r = 0; r < 4; r++) acc[mt][nt][r] = 0.f;

    const int KT = K / BK;

    auto load_tile = [&](int buf, int k0) {
        uint32_t sbase = sb + (uint32_t)(buf * STAGE_B);
        #pragma unroll
        for (int u = 0; u < 4; u++) {
            int ch = tid + u * 256;
            int row = ch >> 3, kq = ch & 7;
            cp_async16(sbase + A_OFF + (uint32_t)(row * ROWB + kq * 16),
                       A + (size_t)(bm + row) * K + k0 + kq * 8);
        }
        #pragma unroll
        for (int u = 0; u < 4; u++) {
            int ch = tid + u * 256;
            int row = ch >> 3, kq = ch & 7;
            cp_async16(sbase + B_OFF + (uint32_t)(row * ROWB + kq * 16),
                       W + (size_t)(bn + row) * K + k0 + kq * 8);
        }
        cp_commit();
    };

    load_tile(0, 0);

    for (int kt = 0; kt < KT; kt++) {
        int cur = kt & 1;
        if (kt + 1 < KT) {
            load_tile(cur ^ 1, (kt + 1) * BK);
            cp_wait<1>();
        } else {
            cp_wait<0>();
        }
        __syncthreads();

        uint32_t soff = (uint32_t)(cur * STAGE_B);
        #pragma unroll
        for (int ks = 0; ks < BK; ks += 16) {
            uint32_t af[2][4], bf[8][2];
            #pragma unroll
            for (int mt = 0; mt < 2; mt++)
                ldsm_x4(af[mt][0], af[mt][1], af[mt][2], af[mt][3],
                        aAddr[mt] + soff + ks * 2);
            #pragma unroll
            for (int p = 0; p < 4; p++)
                ldsm_x4(bf[2 * p][0], bf[2 * p][1], bf[2 * p + 1][0],
                        bf[2 * p + 1][1], bAddr[p] + soff + ks * 2);
            #pragma unroll
            for (int mt = 0; mt < 2; mt++)
                #pragma unroll
                for (int nt = 0; nt < 8; nt++) {
                    asm volatile(
                        "mma.sync.aligned.m16n8k16.row.col.f32.f16.f16.f32 "
                        "{%0,%1,%2,%3}, {%4,%5,%6,%7}, {%8,%9}, {%0,%1,%2,%3};\n"
                        : "+f"(acc[mt][nt][0]), "+f"(acc[mt][nt][1]),
                          "+f"(acc[mt][nt][2]), "+f"(acc[mt][nt][3])
                        : "r"(af[mt][0]), "r"(af[mt][1]), "r"(af[mt][2]), "r"(af[mt][3]),
                          "r"(bf[nt][0]), "r"(bf[nt][1]));
                }
        }
        __syncthreads();
    }

    // epilogue
    #pragma unroll
    for (int mt = 0; mt < 2; mt++) {
        #pragma unroll
        for (int h = 0; h < 2; h++) {
            int row = bm + wm + mt * 16 + lr + h * 8;
            size_t orow = (size_t)row;
            if (mode == 4) {
                int b_ = row >> 12, wi = (row >> 6) & 63, n = row & 63;
                int wh = wi >> 3, ww = wi & 7, i = n >> 3, j = n & 7;
                int sh_ = ((wh * 8 + i) + SSH) & 63;
                int sw_ = ((ww * 8 + j) + SSH) & 63;
                orow = (size_t)b_ * 4096 + sh_ * 64 + sw_;
            }
            #pragma unroll
            for (int nt = 0; nt < 8; nt++) {
                int col = bn + wn + nt * 8 + 2 * lc;
                float v0 = acc[mt][nt][2 * h + 0] + bias[col];
                float v1 = acc[mt][nt][2 * h + 1] + bias[col + 1];
                if (mode == 0) {
                    int which = col >> 9;
                    int hc = col & 511;
                    int head = hc >> 5, d = hc & 31;
                    size_t off = (size_t)which * TCH +
                        ((((size_t)(row >> 6) * NHEADS + head) * 64) +
                         (row & 63)) * 32 + d;
                    *(__half2*)((__half*)Cout + off) = __floats2half2_rn(v0, v1);
                } else if (mode == 1) {
                    v0 = 0.5f * v0 * (1.f + erff(v0 * 0.70710678118654752f));
                    v1 = 0.5f * v1 * (1.f + erff(v1 * 0.70710678118654752f));
                    __half* crow = (__half*)Cout + (size_t)row * N + col;
                    *(__half2*)crow = __floats2half2_rn(v0, v1);
                } else {
                    const float* ar = add + orow * N + col;
                    v0 += ar[0]; v1 += ar[1];
                    float* crow = (float*)Cout + orow * N + col;
                    crow[0] = v0; crow[1] = v1;
                }
            }
        }
    }
}

// ============================ attention ====================================
// one block per (window, head), 64 threads. Head-major qkv. K/V in half2
// smem; QK and PV computed with HFMA2 (no cvt). Probs in half smem.
__global__ __launch_bounds__(64, 12)
void attn_kernel(const __half* __restrict__ qkv, const float* __restrict__ btab,
                 __half* __restrict__ ctx) {
    __shared__ __half2 ks2[64][16];
    __shared__ __half2 vs2[64][16];
    __shared__ __half  sc[64][66];
    __shared__ float   sbias[225];
    __shared__ int     rid[64];

    int win  = blockIdx.x;
    int head = blockIdx.y;
    int n    = threadIdx.x;

    int wi = win & 63;
    int wh = wi >> 3, ww = wi & 7;
    int i  = n  >> 3, j  = n  & 7;

    int hs = wh * 8 + i, wc = ww * 8 + j;
    int rh = (hs < 56) ? 0 : ((hs < 60) ? 1 : 2);
    int rw = (wc < 56) ? 0 : ((wc < 60) ? 1 : 2);
    rid[n] = rh * 3 + rw;

    size_t hbase = (((size_t)win * NHEADS + head) * 64) * 32;  // halves
    {
        const uint4* kp = (const uint4*)(qkv + TCH + hbase + (size_t)n * 32);
        const uint4* vp = (const uint4*)(qkv + 2 * TCH + hbase + (size_t)n * 32);
        #pragma unroll
        for (int u = 0; u < 4; u++) {
            ((uint4*)ks2[n])[u] = kp[u];
            ((uint4*)vs2[n])[u] = vp[u];
        }
    }
    __half2 qh[16];
    {
        const __half2* qp = (const __half2*)(qkv + hbase + (size_t)n * 32);
        #pragma unroll
        for (int u = 0; u < 16; u++) qh[u] = qp[u];
    }
    for (int t = n; t < 225; t += 64) sbias[t] = btab[t * NHEADS + head];
    __syncthreads();

    const float scale = 0.17677669529663687f;
    int myrid = rid[n];

    // QK: half2 FMA, two accumulator chains (length 8 each)
    float mx = -1e30f;
    for (int m = 0; m < 64; m++) {
        const __half2* kr = ks2[m];
        __half2 a0 = __float2half2_rn(0.f);
        __half2 a1 = __float2half2_rn(0.f);
        #pragma unroll
        for (int u = 0; u < 8; u++) {
            a0 = __hfma2(qh[2 * u],     kr[2 * u],     a0);
            a1 = __hfma2(qh[2 * u + 1], kr[2 * u + 1], a1);
        }
        float2 f = __half22float2(__hadd2(a0, a1));
        float acc = f.x + f.y;
        int hk = m >> 3, wk = m & 7;
        int bidx = (i - hk + 7) * 15 + (j - wk + 7);
        float bv = sbias[bidx];
        float msk = (rid[m] == myrid) ? 0.f : -100.f;
        float s = acc * scale + bv + msk;
        sc[n][m] = __float2half(s);
        mx = fmaxf(mx, s);
    }

    float sum = 0.f;
    for (int m = 0; m < 64; m++) {
        float e = __expf(__half2float(sc[n][m]) - mx);
        sc[n][m] = __float2half(e);
        sum += e;
    }
    float inv = 1.f / sum;

    // PV: half2 FMA, even/odd-m accumulator chains (length 32 each)
    __half2 pa[16], pb[16];
    #pragma unroll
    for (int u = 0; u < 16; u++) {
        pa[u] = __float2half2_rn(0.f);
        pb[u] = __float2half2_rn(0.f);
    }
    for (int m = 0; m < 64; m += 2) {
        __half2 p0 = __half2half2(sc[n][m]);
        __half2 p1 = __half2half2(sc[n][m + 1]);
        const __half2* v0 = vs2[m];
        const __half2* v1 = vs2[m + 1];
        #pragma unroll
        for (int u = 0; u < 16; u++) {
            pa[u] = __hfma2(p0, v0[u], pa[u]);
            pb[u] = __hfma2(p1, v1[u], pb[u]);
        }
    }
    __half2 inv2 = __float2half2_rn(inv);
    __half2* o = (__half2*)(ctx + ((size_t)win * 64 + n) * CDIM + head * 32);
    #pragma unroll
    for (int u = 0; u < 16; u++)
        o[u] = __hmul2(__hadd2(pa[u], pb[u]), inv2);
}

// ============================ launch =======================================
extern "C" void kernel_launch(void* const* d_in, const int* in_sizes, int n_in,
                              void* d_out, int out_size) {
    const float* hid    = (const float*)d_in[0];
    const float* q_w    = (const float*)d_in[1];
    const float* q_b    = (const float*)d_in[2];
    const float* k_w    = (const float*)d_in[3];
    const float* k_b    = (const float*)d_in[4];
    const float* v_w    = (const float*)d_in[5];
    const float* v_b    = (const float*)d_in[6];
    const float* proj_w = (const float*)d_in[7];
    const float* proj_b = (const float*)d_in[8];
    const float* relb   = (const float*)d_in[9];
    const float* ln1w   = (const float*)d_in[10];
    const float* ln1b   = (const float*)d_in[11];
    const float* ln2w   = (const float*)d_in[12];
    const float* ln2b   = (const float*)d_in[13];
    const float* fc1w   = (const float*)d_in[14];
    const float* fc1b   = (const float*)d_in[15];
    const float* fc2w   = (const float*)d_in[16];
    const float* fc2b   = (const float*)d_in[17];

    unsigned char* base = nullptr;
    cudaGetSymbolAddress((void**)&base, g_scratch);
    const size_t TC = (size_t)NTOK * CDIM;
    __half* xw   = (__half*)base;
    __half* qkvb = (__half*)(base + TC * 2);
    __half* cx   = (__half*)(base + TC * 8);
    float*  hb   = (float*)(base + TC * 10);
    __half* yb   = (__half*)(base + TC * 14);
    __half* mlp  = (__half*)(base + TC * 16);
    unsigned char* wbase = base + TC * 24;
    const size_t CC = (size_t)CDIM * CDIM, MC = (size_t)MLPD * CDIM;
    __half* wqkv = (__half*)wbase;
    __half* wp   = wqkv + 3 * CC;
    __half* wf1  = wp + CC;
    __half* wf2  = wf1 + MC;
    float*  qkvbias = (float*)(wf2 + MC);

    float* out = (float*)d_out;

    cudaFuncSetAttribute(gemm_f16_kernel,
                         cudaFuncAttributeMaxDynamicSharedMemorySize, GEMM_SMEM);

    convert_weights_kernel<<<3072, 256>>>(q_w, k_w, v_w, proj_w, fc1w, fc2w,
                                          q_b, k_b, v_b,
                                          wqkv, wp, wf1, wf2, qkvbias);

    ln1_gather_kernel<<<NTOK / 8, 256>>>(hid, ln1w, ln1b, xw);

    gemm_f16_kernel<<<dim3(QKVN / BN, NTOK / BM), 256, GEMM_SMEM>>>(
        xw, wqkv, qkvbias, qkvb, QKVN, CDIM, 0, nullptr);

    attn_kernel<<<dim3(1024, NHEADS), 64>>>(qkvb, relb, cx);

    gemm_f16_kernel<<<dim3(CDIM / BN, NTOK / BM), 256, GEMM_SMEM>>>(
        cx, wp, proj_b, hb, CDIM, CDIM, 4, hid);

    ln_plain_kernel<<<NTOK / 8, 256>>>(hb, ln2w, ln2b, yb);

    gemm_f16_kernel<<<dim3(MLPD / BN, NTOK / BM), 256, GEMM_SMEM>>>(
        yb, wf1, fc1b, mlp, MLPD, CDIM, 1, nullptr);

    gemm_f16_kernel<<<dim3(CDIM / BN, NTOK / BM), 256, GEMM_SMEM>>>(
        mlp, wf2, fc2b, out, CDIM, MLPD, 2, hb);
}

// round 15
// speedup vs baseline: 1.2157x; 1.1317x over previous
#include <cuda_runtime.h>
#include <cuda_fp16.h>
#include <math.h>
#include <stdint.h>

// ---------------------------------------------------------------------------
// DonutSwinLayer: B=16, H=W=64, C=512, NH=16, HD=32, WS=8, N=64, SS=4, MLP=2048
// Round 15: attention on tensor cores (mma m16n8k16 for QK and PV),
//           softmax elementwise on fragments. GEMMs/LNs/prepass = R14.
// ---------------------------------------------------------------------------

#define NTOK   65536
#define CDIM   512
#define NHEADS 16
#define HDIM   32
#define SSH    4
#define MLPD   2048
#define QKVN   1536
#define TCH    33554432ULL          // NTOK*CDIM (halves per q/k/v plane)

#define BM 128
#define BN 128
#define BK 64
#define ROWB 144                    // bytes per smem row (72 halves, LDSM-safe)
#define A_OFF 0
#define B_OFF (BM * ROWB)           // 18432
#define STAGE_B ((BM + BN) * ROWB)  // 36864
#define NSTAGE 2
#define GEMM_SMEM (NSTAGE * STAGE_B)   // 73728

__device__ unsigned char g_scratch[(size_t)26 * NTOK * CDIM + (1u << 24)];

// ============================ helpers ======================================
__device__ __forceinline__ void cp_async16(uint32_t s, const void* g) {
    asm volatile("cp.async.cg.shared.global [%0], [%1], 16;" :: "r"(s), "l"(g));
}
__device__ __forceinline__ void cp_commit() {
    asm volatile("cp.async.commit_group;");
}
template<int N_> __device__ __forceinline__ void cp_wait() {
    asm volatile("cp.async.wait_group %0;" :: "n"(N_));
}
__device__ __forceinline__ void ldsm_x4(uint32_t& r0, uint32_t& r1,
                                        uint32_t& r2, uint32_t& r3, uint32_t a) {
    asm volatile("ldmatrix.sync.aligned.m8n8.x4.shared.b16 {%0,%1,%2,%3}, [%4];"
                 : "=r"(r0), "=r"(r1), "=r"(r2), "=r"(r3) : "r"(a));
}
__device__ __forceinline__ void mma_16816(float* d, const uint32_t* a,
                                          const uint32_t* b) {
    asm volatile(
        "mma.sync.aligned.m16n8k16.row.col.f32.f16.f16.f32 "
        "{%0,%1,%2,%3}, {%4,%5,%6,%7}, {%8,%9}, {%0,%1,%2,%3};\n"
        : "+f"(d[0]), "+f"(d[1]), "+f"(d[2]), "+f"(d[3])
        : "r"(a[0]), "r"(a[1]), "r"(a[2]), "r"(a[3]), "r"(b[0]), "r"(b[1]));
}

// single prepass: weights fp32->fp16 + qkv bias concat
__global__ void convert_weights_kernel(
    const float* __restrict__ qw, const float* __restrict__ kw,
    const float* __restrict__ vw, const float* __restrict__ pw,
    const float* __restrict__ f1, const float* __restrict__ f2,
    const float* __restrict__ qb, const float* __restrict__ kb,
    const float* __restrict__ vb,
    __half* __restrict__ wqkv, __half* __restrict__ wp,
    __half* __restrict__ wf1, __half* __restrict__ wf2,
    float* __restrict__ qkvbias) {
    const int CC = 262144, MC = 1048576;
    int gi = blockIdx.x * blockDim.x + threadIdx.x;
    if (gi < 1536) {
        float v = (gi < 512) ? qb[gi] : (gi < 1024 ? kb[gi - 512] : vb[gi - 1024]);
        qkvbias[gi] = v;
    }
    int i = gi * 4;
    const float* src; __half* dst; int off;
    if (i < CC)              { src = qw; dst = wqkv;          off = i; }
    else if (i < 2 * CC)     { src = kw; dst = wqkv + CC;     off = i - CC; }
    else if (i < 3 * CC)     { src = vw; dst = wqkv + 2 * CC; off = i - 2 * CC; }
    else if (i < 4 * CC)     { src = pw; dst = wp;            off = i - 3 * CC; }
    else if (i < 4 * CC + MC){ src = f1; dst = wf1;           off = i - 4 * CC; }
    else                     { src = f2; dst = wf2;           off = i - 4 * CC - MC; }
    float4 v = *(const float4*)(src + off);
    *(__half2*)(dst + off)     = __floats2half2_rn(v.x, v.y);
    *(__half2*)(dst + off + 2) = __floats2half2_rn(v.z, v.w);
}

// ============================ LN kernels (warp per row) ====================
__device__ __forceinline__ void warp_reduce_2(float& s, float& s2) {
    #pragma unroll
    for (int o = 16; o > 0; o >>= 1) {
        s  += __shfl_xor_sync(0xffffffffu, s,  o);
        s2 += __shfl_xor_sync(0xffffffffu, s2, o);
    }
}

__global__ __launch_bounds__(256)
void ln1_gather_kernel(const float* __restrict__ hid,
                       const float* __restrict__ g,
                       const float* __restrict__ b,
                       __half* __restrict__ xw) {
    int wr = blockIdx.x * 8 + (threadIdx.x >> 5);
    int lane = threadIdx.x & 31;
    int b_  = wr >> 12;
    int rem = wr & 4095;
    int wi  = rem >> 6;
    int n   = rem & 63;
    int wh = wi >> 3, ww = wi & 7;
    int i  = n  >> 3, j  = n  & 7;
    int sh_ = ((wh * 8 + i) + SSH) & 63;
    int sw_ = ((ww * 8 + j) + SSH) & 63;
    const float* src = hid + ((size_t)b_ * 4096 + sh_ * 64 + sw_) * CDIM;

    float4 v[4];
    float s = 0.f, s2 = 0.f;
    #pragma unroll
    for (int u = 0; u < 4; u++) {
        v[u] = *(const float4*)(src + lane * 4 + u * 128);
        s  += v[u].x + v[u].y + v[u].z + v[u].w;
        s2 += v[u].x * v[u].x + v[u].y * v[u].y + v[u].z * v[u].z + v[u].w * v[u].w;
    }
    warp_reduce_2(s, s2);
    float mu  = s * (1.f / CDIM);
    float var = s2 * (1.f / CDIM) - mu * mu;
    float inv = rsqrtf(var + 1e-5f);

    __half* dst = xw + (size_t)wr * CDIM;
    #pragma unroll
    for (int u = 0; u < 4; u++) {
        int c = lane * 4 + u * 128;
        float4 gg = *(const float4*)(g + c);
        float4 bb = *(const float4*)(b + c);
        __half2 h0 = __floats2half2_rn((v[u].x - mu) * inv * gg.x + bb.x,
                                       (v[u].y - mu) * inv * gg.y + bb.y);
        __half2 h1 = __floats2half2_rn((v[u].z - mu) * inv * gg.z + bb.z,
                                       (v[u].w - mu) * inv * gg.w + bb.w);
        *(__half2*)(dst + c)     = h0;
        *(__half2*)(dst + c + 2) = h1;
    }
}

__global__ __launch_bounds__(256)
void ln_plain_kernel(const float* __restrict__ x,
                     const float* __restrict__ g,
                     const float* __restrict__ b,
                     __half* __restrict__ y) {
    int r = blockIdx.x * 8 + (threadIdx.x >> 5);
    int lane = threadIdx.x & 31;
    const float* src = x + (size_t)r * CDIM;
    float4 v[4];
    float s = 0.f, s2 = 0.f;
    #pragma unroll
    for (int u = 0; u < 4; u++) {
        v[u] = *(const float4*)(src + lane * 4 + u * 128);
        s  += v[u].x + v[u].y + v[u].z + v[u].w;
        s2 += v[u].x * v[u].x + v[u].y * v[u].y + v[u].z * v[u].z + v[u].w * v[u].w;
    }
    warp_reduce_2(s, s2);
    float mu  = s * (1.f / CDIM);
    float var = s2 * (1.f / CDIM) - mu * mu;
    float inv = rsqrtf(var + 1e-5f);
    __half* dst = y + (size_t)r * CDIM;
    #pragma unroll
    for (int u = 0; u < 4; u++) {
        int c = lane * 4 + u * 128;
        float4 gg = *(const float4*)(g + c);
        float4 bb = *(const float4*)(b + c);
        __half2 h0 = __floats2half2_rn((v[u].x - mu) * inv * gg.x + bb.x,
                                       (v[u].y - mu) * inv * gg.y + bb.y);
        __half2 h1 = __floats2half2_rn((v[u].z - mu) * inv * gg.z + bb.z,
                                       (v[u].w - mu) * inv * gg.w + bb.w);
        *(__half2*)(dst + c)     = h0;
        *(__half2*)(dst + c + 2) = h1;
    }
}

// ============================ fp16 GEMM (frozen) ===========================
// mode: 0 qkv head-major scatter (half), 1 gelu->half, 2 float+residual,
//       4 float+window-reverse-scatter+residual
__global__ __launch_bounds__(256, 2)
void gemm_f16_kernel(const __half* __restrict__ A, const __half* __restrict__ W,
                     const float* __restrict__ bias, void* __restrict__ Cout,
                     int N, int K, int mode, const float* __restrict__ add) {
    extern __shared__ char smem[];
    uint32_t sb = (uint32_t)__cvta_generic_to_shared(smem);

    const int tid  = threadIdx.x;
    const int warp = tid >> 5;
    const int lane = tid & 31;
    const int bm   = blockIdx.y * BM;
    const int bn   = blockIdx.x * BN;
    const int wm   = (warp & 3) * 32;
    const int wn   = (warp >> 2) * 64;
    const int lr   = lane >> 2;
    const int lc   = lane & 3;

    uint32_t aAddr[2], bAddr[4];
    {
        int arow = wm + (lane & 15);
        int akof = (lane >> 4) * 16;
        #pragma unroll
        for (int mt = 0; mt < 2; mt++)
            aAddr[mt] = sb + A_OFF + (uint32_t)((arow + mt * 16) * ROWB + akof);
        int brow = wn + (lane & 7) + ((lane >> 4) << 3);
        int bkof = ((lane >> 3) & 1) << 4;
        #pragma unroll
        for (int p = 0; p < 4; p++)
            bAddr[p] = sb + B_OFF + (uint32_t)((brow + p * 16) * ROWB + bkof);
    }

    float acc[2][8][4];
    #pragma unroll
    for (int mt = 0; mt < 2; mt++)
        #pragma unroll
        for (int nt = 0; nt < 8; nt++)
            #pragma unroll
            for (int r = 0; r < 4; r++) acc[mt][nt][r] = 0.f;

    const int KT = K / BK;

    auto load_tile = [&](int buf, int k0) {
        uint32_t sbase = sb + (uint32_t)(buf * STAGE_B);
        #pragma unroll
        for (int u = 0; u < 4; u++) {
            int ch = tid + u * 256;
            int row = ch >> 3, kq = ch & 7;
            cp_async16(sbase + A_OFF + (uint32_t)(row * ROWB + kq * 16),
                       A + (size_t)(bm + row) * K + k0 + kq * 8);
        }
        #pragma unroll
        for (int u = 0; u < 4; u++) {
            int ch = tid + u * 256;
            int row = ch >> 3, kq = ch & 7;
            cp_async16(sbase + B_OFF + (uint32_t)(row * ROWB + kq * 16),
                       W + (size_t)(bn + row) * K + k0 + kq * 8);
        }
        cp_commit();
    };

    load_tile(0, 0);

    for (int kt = 0; kt < KT; kt++) {
        int cur = kt & 1;
        if (kt + 1 < KT) {
            load_tile(cur ^ 1, (kt + 1) * BK);
            cp_wait<1>();
        } else {
            cp_wait<0>();
        }
        __syncthreads();

        uint32_t soff = (uint32_t)(cur * STAGE_B);
        #pragma unroll
        for (int ks = 0; ks < BK; ks += 16) {
            uint32_t af[2][4], bf[8][2];
            #pragma unroll
            for (int mt = 0; mt < 2; mt++)
                ldsm_x4(af[mt][0], af[mt][1], af[mt][2], af[mt][3],
                        aAddr[mt] + soff + ks * 2);
            #pragma unroll
            for (int p = 0; p < 4; p++)
                ldsm_x4(bf[2 * p][0], bf[2 * p][1], bf[2 * p + 1][0],
                        bf[2 * p + 1][1], bAddr[p] + soff + ks * 2);
            #pragma unroll
            for (int mt = 0; mt < 2; mt++)
                #pragma unroll
                for (int nt = 0; nt < 8; nt++)
                    mma_16816(acc[mt][nt], af[mt], bf[nt]);
        }
        __syncthreads();
    }

    // epilogue
    #pragma unroll
    for (int mt = 0; mt < 2; mt++) {
        #pragma unroll
        for (int h = 0; h < 2; h++) {
            int row = bm + wm + mt * 16 + lr + h * 8;
            size_t orow = (size_t)row;
            if (mode == 4) {
                int b_ = row >> 12, wi = (row >> 6) & 63, n = row & 63;
                int wh = wi >> 3, ww = wi & 7, i = n >> 3, j = n & 7;
                int sh_ = ((wh * 8 + i) + SSH) & 63;
                int sw_ = ((ww * 8 + j) + SSH) & 63;
                orow = (size_t)b_ * 4096 + sh_ * 64 + sw_;
            }
            #pragma unroll
            for (int nt = 0; nt < 8; nt++) {
                int col = bn + wn + nt * 8 + 2 * lc;
                float v0 = acc[mt][nt][2 * h + 0] + bias[col];
                float v1 = acc[mt][nt][2 * h + 1] + bias[col + 1];
                if (mode == 0) {
                    int which = col >> 9;
                    int hc = col & 511;
                    int head = hc >> 5, d = hc & 31;
                    size_t off = (size_t)which * TCH +
                        ((((size_t)(row >> 6) * NHEADS + head) * 64) +
                         (row & 63)) * 32 + d;
                    *(__half2*)((__half*)Cout + off) = __floats2half2_rn(v0, v1);
                } else if (mode == 1) {
                    v0 = 0.5f * v0 * (1.f + erff(v0 * 0.70710678118654752f));
                    v1 = 0.5f * v1 * (1.f + erff(v1 * 0.70710678118654752f));
                    __half* crow = (__half*)Cout + (size_t)row * N + col;
                    *(__half2*)crow = __floats2half2_rn(v0, v1);
                } else {
                    const float* ar = add + orow * N + col;
                    v0 += ar[0]; v1 += ar[1];
                    float* crow = (float*)Cout + orow * N + col;
                    crow[0] = v0; crow[1] = v1;
                }
            }
        }
    }
}

// ============================ attention (tensor core) ======================
// one block per (window, head), 64 threads = 2 warps; warp w owns query rows
// [32w, 32w+32). QK and PV via mma m16n8k16, softmax on fp32 fragments.
// Q/K smem rows: 32 halves + pad -> 80B stride (conflict-free ldmatrix).
// V stored transposed [d][m] and P [n][m] at 144B stride (GEMM-proven).
__global__ __launch_bounds__(64, 9)
void attn_kernel(const __half* __restrict__ qkv, const float* __restrict__ btab,
                 __half* __restrict__ ctx) {
    __shared__ __align__(16) __half qs[64][40];
    __shared__ __align__(16) __half ks[64][40];
    __shared__ __align__(16) __half vt[32][72];   // V^T [d][m]
    __shared__ __align__(16) __half sc[64][72];   // P   [n][m]
    __shared__ float sbias[225];
    __shared__ int   rid[64];

    int win  = blockIdx.x;
    int head = blockIdx.y;
    int tid  = threadIdx.x;
    int warp = tid >> 5;
    int lane = tid & 31;
    int n    = tid;   // fill row

    int wi = win & 63;
    int wh = wi >> 3, ww = wi & 7;
    {
        int i = n >> 3, j = n & 7;
        int hs = wh * 8 + i, wc = ww * 8 + j;
        int rh = (hs < 56) ? 0 : ((hs < 60) ? 1 : 2);
        int rw = (wc < 56) ? 0 : ((wc < 60) ? 1 : 2);
        rid[n] = rh * 3 + rw;
    }

    size_t hbase = (((size_t)win * NHEADS + head) * 64) * 32;  // halves
    {
        const uint4* qp = (const uint4*)(qkv + hbase + (size_t)n * 32);
        const uint4* kp = (const uint4*)(qkv + TCH + hbase + (size_t)n * 32);
        #pragma unroll
        for (int u = 0; u < 4; u++) {
            ((uint4*)qs[n])[u] = qp[u];
            ((uint4*)ks[n])[u] = kp[u];
        }
        const uint4* vp = (const uint4*)(qkv + 2 * TCH + hbase + (size_t)n * 32);
        __half vr[32];
        #pragma unroll
        for (int u = 0; u < 4; u++) ((uint4*)vr)[u] = vp[u];
        #pragma unroll
        for (int d = 0; d < 32; d++) vt[d][n] = vr[d];
    }
    for (int t = tid; t < 225; t += 64) sbias[t] = btab[t * NHEADS + head];
    __syncthreads();

    uint32_t sqs = (uint32_t)__cvta_generic_to_shared(qs);
    uint32_t sks = (uint32_t)__cvta_generic_to_shared(ks);
    uint32_t svt = (uint32_t)__cvta_generic_to_shared(vt);
    uint32_t ssc = (uint32_t)__cvta_generic_to_shared(sc);

    // ---------------- QK^T via mma: M=32(warp), N=64, K=32 ----------------
    float acc[2][8][4];
    #pragma unroll
    for (int mt = 0; mt < 2; mt++)
        #pragma unroll
        for (int nt = 0; nt < 8; nt++)
            #pragma unroll
            for (int r = 0; r < 4; r++) acc[mt][nt][r] = 0.f;
    {
        uint32_t qa[2], ka[4];
        int arow = warp * 32 + (lane & 15);
        int akof = (lane >> 4) * 16;   // bytes
        #pragma unroll
        for (int mt = 0; mt < 2; mt++)
            qa[mt] = sqs + (uint32_t)((arow + mt * 16) * 80 + akof);
        int brow = (lane & 7) + ((lane >> 4) << 3);
        int bkof = ((lane >> 3) & 1) << 4;   // bytes
        #pragma unroll
        for (int p = 0; p < 4; p++)
            ka[p] = sks + (uint32_t)((brow + p * 16) * 80 + bkof);

        #pragma unroll
        for (int kk = 0; kk < 32; kk += 16) {
            uint32_t af[2][4], bf[8][2];
            #pragma unroll
            for (int mt = 0; mt < 2; mt++)
                ldsm_x4(af[mt][0], af[mt][1], af[mt][2], af[mt][3],
                        qa[mt] + kk * 2);
            #pragma unroll
            for (int p = 0; p < 4; p++)
                ldsm_x4(bf[2 * p][0], bf[2 * p][1], bf[2 * p + 1][0],
                        bf[2 * p + 1][1], ka[p] + kk * 2);
            #pragma unroll
            for (int mt = 0; mt < 2; mt++)
                #pragma unroll
                for (int nt = 0; nt < 8; nt++)
                    mma_16816(acc[mt][nt], af[mt], bf[nt]);
        }
    }

    // ---------------- softmax on fragments ----------------
    const float scale = 0.17677669529663687f;
    float mx[2][2] = {{-1e30f, -1e30f}, {-1e30f, -1e30f}};
    #pragma unroll
    for (int mt = 0; mt < 2; mt++)
        #pragma unroll
        for (int h = 0; h < 2; h++) {
            int nq = warp * 32 + mt * 16 + (lane >> 2) + 8 * h;
            int iq = nq >> 3, jq = nq & 7;
            int ridn = rid[nq];
            #pragma unroll
            for (int nt = 0; nt < 8; nt++)
                #pragma unroll
                for (int c = 0; c < 2; c++) {
                    int mk = nt * 8 + 2 * (lane & 3) + c;
                    int hk = mk >> 3, wk = mk & 7;
                    float bv = sbias[(iq - hk + 7) * 15 + (jq - wk + 7)];
                    float msk = (rid[mk] == ridn) ? 0.f : -100.f;
                    float s = acc[mt][nt][2 * h + c] * scale + bv + msk;
                    acc[mt][nt][2 * h + c] = s;
                    mx[mt][h] = fmaxf(mx[mt][h], s);
                }
        }
    #pragma unroll
    for (int mt = 0; mt < 2; mt++)
        #pragma unroll
        for (int h = 0; h < 2; h++) {
            float m0 = mx[mt][h];
            m0 = fmaxf(m0, __shfl_xor_sync(0xffffffffu, m0, 1));
            m0 = fmaxf(m0, __shfl_xor_sync(0xffffffffu, m0, 2));
            mx[mt][h] = m0;
        }
    float sum[2][2] = {{0.f, 0.f}, {0.f, 0.f}};
    #pragma unroll
    for (int mt = 0; mt < 2; mt++)
        #pragma unroll
        for (int h = 0; h < 2; h++) {
            int nq = warp * 32 + mt * 16 + (lane >> 2) + 8 * h;
            #pragma unroll
            for (int nt = 0; nt < 8; nt++) {
                float e0 = __expf(acc[mt][nt][2 * h + 0] - mx[mt][h]);
                float e1 = __expf(acc[mt][nt][2 * h + 1] - mx[mt][h]);
                sum[mt][h] += e0 + e1;
                *(__half2*)&sc[nq][nt * 8 + 2 * (lane & 3)] =
                    __floats2half2_rn(e0, e1);
            }
        }
    #pragma unroll
    for (int mt = 0; mt < 2; mt++)
        #pragma unroll
        for (int h = 0; h < 2; h++) {
            float s0 = sum[mt][h];
            s0 += __shfl_xor_sync(0xffffffffu, s0, 1);
            s0 += __shfl_xor_sync(0xffffffffu, s0, 2);
            sum[mt][h] = 1.f / s0;
        }
    __syncwarp();

    // ---------------- PV via mma: M=32(warp), N=32, K=64 -------------------
    float accd[2][4][4];
    #pragma unroll
    for (int mt = 0; mt < 2; mt++)
        #pragma unroll
        for (int nt = 0; nt < 4; nt++)
            #pragma unroll
            for (int r = 0; r < 4; r++) accd[mt][nt][r] = 0.f;
    {
        uint32_t pa[2], va[2];
        int arow = warp * 32 + (lane & 15);
        int akof = (lane >> 4) * 16;
        #pragma unroll
        for (int mt = 0; mt < 2; mt++)
            pa[mt] = ssc + (uint32_t)((arow + mt * 16) * 144 + akof);
        int brow = (lane & 7) + ((lane >> 4) << 3);
        int bkof = ((lane >> 3) & 1) << 4;
        #pragma unroll
        for (int p = 0; p < 2; p++)
            va[p] = svt + (uint32_t)((brow + p * 16) * 144 + bkof);

        #pragma unroll
        for (int kk = 0; kk < 64; kk += 16) {
            uint32_t af[2][4], bf[4][2];
            #pragma unroll
            for (int mt = 0; mt < 2; mt++)
                ldsm_x4(af[mt][0], af[mt][1], af[mt][2], af[mt][3],
                        pa[mt] + kk * 2);
            #pragma unroll
            for (int p = 0; p < 2; p++)
                ldsm_x4(bf[2 * p][0], bf[2 * p][1], bf[2 * p + 1][0],
                        bf[2 * p + 1][1], va[p] + kk * 2);
            #pragma unroll
            for (int mt = 0; mt < 2; mt++)
                #pragma unroll
                for (int nt = 0; nt < 4; nt++)
                    mma_16816(accd[mt][nt], af[mt], bf[nt]);
        }
    }

    // ---------------- write ctx ----------------
    #pragma unroll
    for (int mt = 0; mt < 2; mt++)
        #pragma unroll
        for (int h = 0; h < 2; h++) {
            int nq = warp * 32 + mt * 16 + (lane >> 2) + 8 * h;
            float inv = sum[mt][h];
            __half* o = ctx + ((size_t)win * 64 + nq) * CDIM + head * 32;
            #pragma unroll
            for (int nt = 0; nt < 4; nt++) {
                int d = nt * 8 + 2 * (lane & 3);
                *(__half2*)(o + d) =
                    __floats2half2_rn(accd[mt][nt][2 * h + 0] * inv,
                                      accd[mt][nt][2 * h + 1] * inv);
            }
        }
}

// ============================ launch =======================================
extern "C" void kernel_launch(void* const* d_in, const int* in_sizes, int n_in,
                              void* d_out, int out_size) {
    const float* hid    = (const float*)d_in[0];
    const float* q_w    = (const float*)d_in[1];
    const float* q_b    = (const float*)d_in[2];
    const float* k_w    = (const float*)d_in[3];
    const float* k_b    = (const float*)d_in[4];
    const float* v_w    = (const float*)d_in[5];
    const float* v_b    = (const float*)d_in[6];
    const float* proj_w = (const float*)d_in[7];
    const float* proj_b = (const float*)d_in[8];
    const float* relb   = (const float*)d_in[9];
    const float* ln1w   = (const float*)d_in[10];
    const float* ln1b   = (const float*)d_in[11];
    const float* ln2w   = (const float*)d_in[12];
    const float* ln2b   = (const float*)d_in[13];
    const float* fc1w   = (const float*)d_in[14];
    const float* fc1b   = (const float*)d_in[15];
    const float* fc2w   = (const float*)d_in[16];
    const float* fc2b   = (const float*)d_in[17];

    unsigned char* base = nullptr;
    cudaGetSymbolAddress((void**)&base, g_scratch);
    const size_t TC = (size_t)NTOK * CDIM;
    __half* xw   = (__half*)base;
    __half* qkvb = (__half*)(base + TC * 2);
    __half* cx   = (__half*)(base + TC * 8);
    float*  hb   = (float*)(base + TC * 10);
    __half* yb   = (__half*)(base + TC * 14);
    __half* mlp  = (__half*)(base + TC * 16);
    unsigned char* wbase = base + TC * 24;
    const size_t CC = (size_t)CDIM * CDIM, MC = (size_t)MLPD * CDIM;
    __half* wqkv = (__half*)wbase;
    __half* wp   = wqkv + 3 * CC;
    __half* wf1  = wp + CC;
    __half* wf2  = wf1 + MC;
    float*  qkvbias = (float*)(wf2 + MC);

    float* out = (float*)d_out;

    cudaFuncSetAttribute(gemm_f16_kernel,
                         cudaFuncAttributeMaxDynamicSharedMemorySize, GEMM_SMEM);

    convert_weights_kernel<<<3072, 256>>>(q_w, k_w, v_w, proj_w, fc1w, fc2w,
                                          q_b, k_b, v_b,
                                          wqkv, wp, wf1, wf2, qkvbias);

    ln1_gather_kernel<<<NTOK / 8, 256>>>(hid, ln1w, ln1b, xw);

    gemm_f16_kernel<<<dim3(QKVN / BN, NTOK / BM), 256, GEMM_SMEM>>>(
        xw, wqkv, qkvbias, qkvb, QKVN, CDIM, 0, nullptr);

    attn_kernel<<<dim3(1024, NHEADS), 64>>>(qkvb, relb, cx);

    gemm_f16_kernel<<<dim3(CDIM / BN, NTOK / BM), 256, GEMM_SMEM>>>(
        cx, wp, proj_b, hb, CDIM, CDIM, 4, hid);

    ln_plain_kernel<<<NTOK / 8, 256>>>(hb, ln2w, ln2b, yb);

    gemm_f16_kernel<<<dim3(MLPD / BN, NTOK / BM), 256, GEMM_SMEM>>>(
        yb, wf1, fc1b, mlp, MLPD, CDIM, 1, nullptr);

    gemm_f16_kernel<<<dim3(CDIM / BN, NTOK / BM), 256, GEMM_SMEM>>>(
        mlp, wf2, fc2b, out, CDIM, MLPD, 2, hb);
}

// round 16
// speedup vs baseline: 1.2219x; 1.0051x over previous
#include <cuda_runtime.h>
#include <cuda_fp16.h>
#include <math.h>
#include <stdint.h>

// ---------------------------------------------------------------------------
// DonutSwinLayer: B=16, H=W=64, C=512, NH=16, HD=32, WS=8, N=64, SS=4, MLP=2048
// Round 16: GEMM BK=64 + 3-stage + single sync/iter. Attention/LN/prepass=R15.
// ---------------------------------------------------------------------------

#define NTOK   65536
#define CDIM   512
#define NHEADS 16
#define HDIM   32
#define SSH    4
#define MLPD   2048
#define QKVN   1536
#define TCH    33554432ULL          // NTOK*CDIM (halves per q/k/v plane)

#define BM 128
#define BN 128
#define BK 64
#define ROWB 144                    // bytes per smem row (72 halves, LDSM-safe)
#define A_OFF 0
#define B_OFF (BM * ROWB)           // 18432
#define STAGE_B ((BM + BN) * ROWB)  // 36864
#define NSTAGE 3
#define GEMM_SMEM (NSTAGE * STAGE_B)   // 110592

__device__ unsigned char g_scratch[(size_t)26 * NTOK * CDIM + (1u << 24)];

// ============================ helpers ======================================
__device__ __forceinline__ void cp_async16(uint32_t s, const void* g) {
    asm volatile("cp.async.cg.shared.global [%0], [%1], 16;" :: "r"(s), "l"(g));
}
__device__ __forceinline__ void cp_commit() {
    asm volatile("cp.async.commit_group;");
}
template<int N_> __device__ __forceinline__ void cp_wait() {
    asm volatile("cp.async.wait_group %0;" :: "n"(N_));
}
__device__ __forceinline__ void ldsm_x4(uint32_t& r0, uint32_t& r1,
                                        uint32_t& r2, uint32_t& r3, uint32_t a) {
    asm volatile("ldmatrix.sync.aligned.m8n8.x4.shared.b16 {%0,%1,%2,%3}, [%4];"
                 : "=r"(r0), "=r"(r1), "=r"(r2), "=r"(r3) : "r"(a));
}
__device__ __forceinline__ void mma_16816(float* d, const uint32_t* a,
                                          const uint32_t* b) {
    asm volatile(
        "mma.sync.aligned.m16n8k16.row.col.f32.f16.f16.f32 "
        "{%0,%1,%2,%3}, {%4,%5,%6,%7}, {%8,%9}, {%0,%1,%2,%3};\n"
        : "+f"(d[0]), "+f"(d[1]), "+f"(d[2]), "+f"(d[3])
        : "r"(a[0]), "r"(a[1]), "r"(a[2]), "r"(a[3]), "r"(b[0]), "r"(b[1]));
}

// single prepass: weights fp32->fp16 + qkv bias concat
__global__ void convert_weights_kernel(
    const float* __restrict__ qw, const float* __restrict__ kw,
    const float* __restrict__ vw, const float* __restrict__ pw,
    const float* __restrict__ f1, const float* __restrict__ f2,
    const float* __restrict__ qb, const float* __restrict__ kb,
    const float* __restrict__ vb,
    __half* __restrict__ wqkv, __half* __restrict__ wp,
    __half* __restrict__ wf1, __half* __restrict__ wf2,
    float* __restrict__ qkvbias) {
    const int CC = 262144, MC = 1048576;
    int gi = blockIdx.x * blockDim.x + threadIdx.x;
    if (gi < 1536) {
        float v = (gi < 512) ? qb[gi] : (gi < 1024 ? kb[gi - 512] : vb[gi - 1024]);
        qkvbias[gi] = v;
    }
    int i = gi * 4;
    const float* src; __half* dst; int off;
    if (i < CC)              { src = qw; dst = wqkv;          off = i; }
    else if (i < 2 * CC)     { src = kw; dst = wqkv + CC;     off = i - CC; }
    else if (i < 3 * CC)     { src = vw; dst = wqkv + 2 * CC; off = i - 2 * CC; }
    else if (i < 4 * CC)     { src = pw; dst = wp;            off = i - 3 * CC; }
    else if (i < 4 * CC + MC){ src = f1; dst = wf1;           off = i - 4 * CC; }
    else                     { src = f2; dst = wf2;           off = i - 4 * CC - MC; }
    float4 v = *(const float4*)(src + off);
    *(__half2*)(dst + off)     = __floats2half2_rn(v.x, v.y);
    *(__half2*)(dst + off + 2) = __floats2half2_rn(v.z, v.w);
}

// ============================ LN kernels (warp per row) ====================
__device__ __forceinline__ void warp_reduce_2(float& s, float& s2) {
    #pragma unroll
    for (int o = 16; o > 0; o >>= 1) {
        s  += __shfl_xor_sync(0xffffffffu, s,  o);
        s2 += __shfl_xor_sync(0xffffffffu, s2, o);
    }
}

__global__ __launch_bounds__(256)
void ln1_gather_kernel(const float* __restrict__ hid,
                       const float* __restrict__ g,
                       const float* __restrict__ b,
                       __half* __restrict__ xw) {
    int wr = blockIdx.x * 8 + (threadIdx.x >> 5);
    int lane = threadIdx.x & 31;
    int b_  = wr >> 12;
    int rem = wr & 4095;
    int wi  = rem >> 6;
    int n   = rem & 63;
    int wh = wi >> 3, ww = wi & 7;
    int i  = n  >> 3, j  = n  & 7;
    int sh_ = ((wh * 8 + i) + SSH) & 63;
    int sw_ = ((ww * 8 + j) + SSH) & 63;
    const float* src = hid + ((size_t)b_ * 4096 + sh_ * 64 + sw_) * CDIM;

    float4 v[4];
    float s = 0.f, s2 = 0.f;
    #pragma unroll
    for (int u = 0; u < 4; u++) {
        v[u] = *(const float4*)(src + lane * 4 + u * 128);
        s  += v[u].x + v[u].y + v[u].z + v[u].w;
        s2 += v[u].x * v[u].x + v[u].y * v[u].y + v[u].z * v[u].z + v[u].w * v[u].w;
    }
    warp_reduce_2(s, s2);
    float mu  = s * (1.f / CDIM);
    float var = s2 * (1.f / CDIM) - mu * mu;
    float inv = rsqrtf(var + 1e-5f);

    __half* dst = xw + (size_t)wr * CDIM;
    #pragma unroll
    for (int u = 0; u < 4; u++) {
        int c = lane * 4 + u * 128;
        float4 gg = *(const float4*)(g + c);
        float4 bb = *(const float4*)(b + c);
        __half2 h0 = __floats2half2_rn((v[u].x - mu) * inv * gg.x + bb.x,
                                       (v[u].y - mu) * inv * gg.y + bb.y);
        __half2 h1 = __floats2half2_rn((v[u].z - mu) * inv * gg.z + bb.z,
                                       (v[u].w - mu) * inv * gg.w + bb.w);
        *(__half2*)(dst + c)     = h0;
        *(__half2*)(dst + c + 2) = h1;
    }
}

__global__ __launch_bounds__(256)
void ln_plain_kernel(const float* __restrict__ x,
                     const float* __restrict__ g,
                     const float* __restrict__ b,
                     __half* __restrict__ y) {
    int r = blockIdx.x * 8 + (threadIdx.x >> 5);
    int lane = threadIdx.x & 31;
    const float* src = x + (size_t)r * CDIM;
    float4 v[4];
    float s = 0.f, s2 = 0.f;
    #pragma unroll
    for (int u = 0; u < 4; u++) {
        v[u] = *(const float4*)(src + lane * 4 + u * 128);
        s  += v[u].x + v[u].y + v[u].z + v[u].w;
        s2 += v[u].x * v[u].x + v[u].y * v[u].y + v[u].z * v[u].z + v[u].w * v[u].w;
    }
    warp_reduce_2(s, s2);
    float mu  = s * (1.f / CDIM);
    float var = s2 * (1.f / CDIM) - mu * mu;
    float inv = rsqrtf(var + 1e-5f);
    __half* dst = y + (size_t)r * CDIM;
    #pragma unroll
    for (int u = 0; u < 4; u++) {
        int c = lane * 4 + u * 128;
        float4 gg = *(const float4*)(g + c);
        float4 bb = *(const float4*)(b + c);
        __half2 h0 = __floats2half2_rn((v[u].x - mu) * inv * gg.x + bb.x,
                                       (v[u].y - mu) * inv * gg.y + bb.y);
        __half2 h1 = __floats2half2_rn((v[u].z - mu) * inv * gg.z + bb.z,
                                       (v[u].w - mu) * inv * gg.w + bb.w);
        *(__half2*)(dst + c)     = h0;
        *(__half2*)(dst + c + 2) = h1;
    }
}

// ============================ fp16 GEMM ====================================
// BK=64, 3 stages, ONE __syncthreads per kt iteration.
// mode: 0 qkv head-major scatter (half), 1 gelu->half, 2 float+residual,
//       4 float+window-reverse-scatter+residual
__global__ __launch_bounds__(256, 2)
void gemm_f16_kernel(const __half* __restrict__ A, const __half* __restrict__ W,
                     const float* __restrict__ bias, void* __restrict__ Cout,
                     int N, int K, int mode, const float* __restrict__ add) {
    extern __shared__ char smem[];
    uint32_t sb = (uint32_t)__cvta_generic_to_shared(smem);

    const int tid  = threadIdx.x;
    const int warp = tid >> 5;
    const int lane = tid & 31;
    const int bm   = blockIdx.y * BM;
    const int bn   = blockIdx.x * BN;
    const int wm   = (warp & 3) * 32;
    const int wn   = (warp >> 2) * 64;
    const int lr   = lane >> 2;
    const int lc   = lane & 3;

    uint32_t aAddr[2], bAddr[4];
    {
        int arow = wm + (lane & 15);
        int akof = (lane >> 4) * 16;
        #pragma unroll
        for (int mt = 0; mt < 2; mt++)
            aAddr[mt] = sb + A_OFF + (uint32_t)((arow + mt * 16) * ROWB + akof);
        int brow = wn + (lane & 7) + ((lane >> 4) << 3);
        int bkof = ((lane >> 3) & 1) << 4;
        #pragma unroll
        for (int p = 0; p < 4; p++)
            bAddr[p] = sb + B_OFF + (uint32_t)((brow + p * 16) * ROWB + bkof);
    }

    float acc[2][8][4];
    #pragma unroll
    for (int mt = 0; mt < 2; mt++)
        #pragma unroll
        for (int nt = 0; nt < 8; nt++)
            #pragma unroll
            for (int r = 0; r < 4; r++) acc[mt][nt][r] = 0.f;

    const int KT = K / BK;

    auto load_tile = [&](int buf, int k0) {
        uint32_t sbase = sb + (uint32_t)(buf * STAGE_B);
        #pragma unroll
        for (int u = 0; u < 4; u++) {
            int ch = tid + u * 256;
            int row = ch >> 3, kq = ch & 7;
            cp_async16(sbase + A_OFF + (uint32_t)(row * ROWB + kq * 16),
                       A + (size_t)(bm + row) * K + k0 + kq * 8);
        }
        #pragma unroll
        for (int u = 0; u < 4; u++) {
            int ch = tid + u * 256;
            int row = ch >> 3, kq = ch & 7;
            cp_async16(sbase + B_OFF + (uint32_t)(row * ROWB + kq * 16),
                       W + (size_t)(bn + row) * K + k0 + kq * 8);
        }
        cp_commit();
    };

    load_tile(0, 0);
    load_tile(1, BK);

    int buf = 0;
    for (int kt = 0; kt < KT; kt++) {
        if (kt < KT - 1) cp_wait<1>(); else cp_wait<0>();
        __syncthreads();
        if (kt + 2 < KT) {
            int nb = buf + 2; if (nb >= NSTAGE) nb -= NSTAGE;
            load_tile(nb, (kt + 2) * BK);
        }

        uint32_t soff = (uint32_t)(buf * STAGE_B);
        #pragma unroll
        for (int ks = 0; ks < BK; ks += 16) {
            uint32_t af[2][4], bf[8][2];
            #pragma unroll
            for (int mt = 0; mt < 2; mt++)
                ldsm_x4(af[mt][0], af[mt][1], af[mt][2], af[mt][3],
                        aAddr[mt] + soff + ks * 2);
            #pragma unroll
            for (int p = 0; p < 4; p++)
                ldsm_x4(bf[2 * p][0], bf[2 * p][1], bf[2 * p + 1][0],
                        bf[2 * p + 1][1], bAddr[p] + soff + ks * 2);
            #pragma unroll
            for (int mt = 0; mt < 2; mt++)
                #pragma unroll
                for (int nt = 0; nt < 8; nt++)
                    mma_16816(acc[mt][nt], af[mt], bf[nt]);
        }
        buf++; if (buf >= NSTAGE) buf = 0;
    }

    // epilogue
    #pragma unroll
    for (int mt = 0; mt < 2; mt++) {
        #pragma unroll
        for (int h = 0; h < 2; h++) {
            int row = bm + wm + mt * 16 + lr + h * 8;
            size_t orow = (size_t)row;
            if (mode == 4) {
                int b_ = row >> 12, wi = (row >> 6) & 63, n = row & 63;
                int wh = wi >> 3, ww = wi & 7, i = n >> 3, j = n & 7;
                int sh_ = ((wh * 8 + i) + SSH) & 63;
                int sw_ = ((ww * 8 + j) + SSH) & 63;
                orow = (size_t)b_ * 4096 + sh_ * 64 + sw_;
            }
            #pragma unroll
            for (int nt = 0; nt < 8; nt++) {
                int col = bn + wn + nt * 8 + 2 * lc;
                float v0 = acc[mt][nt][2 * h + 0] + bias[col];
                float v1 = acc[mt][nt][2 * h + 1] + bias[col + 1];
                if (mode == 0) {
                    int which = col >> 9;
                    int hc = col & 511;
                    int head = hc >> 5, d = hc & 31;
                    size_t off = (size_t)which * TCH +
                        ((((size_t)(row >> 6) * NHEADS + head) * 64) +
                         (row & 63)) * 32 + d;
                    *(__half2*)((__half*)Cout + off) = __floats2half2_rn(v0, v1);
                } else if (mode == 1) {
                    v0 = 0.5f * v0 * (1.f + erff(v0 * 0.70710678118654752f));
                    v1 = 0.5f * v1 * (1.f + erff(v1 * 0.70710678118654752f));
                    __half* crow = (__half*)Cout + (size_t)row * N + col;
                    *(__half2*)crow = __floats2half2_rn(v0, v1);
                } else {
                    const float* ar = add + orow * N + col;
                    v0 += ar[0]; v1 += ar[1];
                    float* crow = (float*)Cout + orow * N + col;
                    crow[0] = v0; crow[1] = v1;
                }
            }
        }
    }
}

// ============================ attention (tensor core, R15) =================
__global__ __launch_bounds__(64, 9)
void attn_kernel(const __half* __restrict__ qkv, const float* __restrict__ btab,
                 __half* __restrict__ ctx) {
    __shared__ __align__(16) __half qs[64][40];
    __shared__ __align__(16) __half ks[64][40];
    __shared__ __align__(16) __half vt[32][72];   // V^T [d][m]
    __shared__ __align__(16) __half sc[64][72];   // P   [n][m]
    __shared__ float sbias[225];
    __shared__ int   rid[64];

    int win  = blockIdx.x;
    int head = blockIdx.y;
    int tid  = threadIdx.x;
    int warp = tid >> 5;
    int lane = tid & 31;
    int n    = tid;

    int wi = win & 63;
    int wh = wi >> 3, ww = wi & 7;
    {
        int i = n >> 3, j = n & 7;
        int hs = wh * 8 + i, wc = ww * 8 + j;
        int rh = (hs < 56) ? 0 : ((hs < 60) ? 1 : 2);
        int rw = (wc < 56) ? 0 : ((wc < 60) ? 1 : 2);
        rid[n] = rh * 3 + rw;
    }

    size_t hbase = (((size_t)win * NHEADS + head) * 64) * 32;
    {
        const uint4* qp = (const uint4*)(qkv + hbase + (size_t)n * 32);
        const uint4* kp = (const uint4*)(qkv + TCH + hbase + (size_t)n * 32);
        #pragma unroll
        for (int u = 0; u < 4; u++) {
            ((uint4*)qs[n])[u] = qp[u];
            ((uint4*)ks[n])[u] = kp[u];
        }
        const uint4* vp = (const uint4*)(qkv + 2 * TCH + hbase + (size_t)n * 32);
        __half vr[32];
        #pragma unroll
        for (int u = 0; u < 4; u++) ((uint4*)vr)[u] = vp[u];
        #pragma unroll
        for (int d = 0; d < 32; d++) vt[d][n] = vr[d];
    }
    for (int t = tid; t < 225; t += 64) sbias[t] = btab[t * NHEADS + head];
    __syncthreads();

    uint32_t sqs = (uint32_t)__cvta_generic_to_shared(qs);
    uint32_t sks = (uint32_t)__cvta_generic_to_shared(ks);
    uint32_t svt = (uint32_t)__cvta_generic_to_shared(vt);
    uint32_t ssc = (uint32_t)__cvta_generic_to_shared(sc);

    float acc[2][8][4];
    #pragma unroll
    for (int mt = 0; mt < 2; mt++)
        #pragma unroll
        for (int nt = 0; nt < 8; nt++)
            #pragma unroll
            for (int r = 0; r < 4; r++) acc[mt][nt][r] = 0.f;
    {
        uint32_t qa[2], ka[4];
        int arow = warp * 32 + (lane & 15);
        int akof = (lane >> 4) * 16;
        #pragma unroll
        for (int mt = 0; mt < 2; mt++)
            qa[mt] = sqs + (uint32_t)((arow + mt * 16) * 80 + akof);
        int brow = (lane & 7) + ((lane >> 4) << 3);
        int bkof = ((lane >> 3) & 1) << 4;
        #pragma unroll
        for (int p = 0; p < 4; p++)
            ka[p] = sks + (uint32_t)((brow + p * 16) * 80 + bkof);

        #pragma unroll
        for (int kk = 0; kk < 32; kk += 16) {
            uint32_t af[2][4], bf[8][2];
            #pragma unroll
            for (int mt = 0; mt < 2; mt++)
                ldsm_x4(af[mt][0], af[mt][1], af[mt][2], af[mt][3],
                        qa[mt] + kk * 2);
            #pragma unroll
            for (int p = 0; p < 4; p++)
                ldsm_x4(bf[2 * p][0], bf[2 * p][1], bf[2 * p + 1][0],
                        bf[2 * p + 1][1], ka[p] + kk * 2);
            #pragma unroll
            for (int mt = 0; mt < 2; mt++)
                #pragma unroll
                for (int nt = 0; nt < 8; nt++)
                    mma_16816(acc[mt][nt], af[mt], bf[nt]);
        }
    }

    const float scale = 0.17677669529663687f;
    float mx[2][2] = {{-1e30f, -1e30f}, {-1e30f, -1e30f}};
    #pragma unroll
    for (int mt = 0; mt < 2; mt++)
        #pragma unroll
        for (int h = 0; h < 2; h++) {
            int nq = warp * 32 + mt * 16 + (lane >> 2) + 8 * h;
            int iq = nq >> 3, jq = nq & 7;
            int ridn = rid[nq];
            #pragma unroll
            for (int nt = 0; nt < 8; nt++)
                #pragma unroll
                for (int c = 0; c < 2; c++) {
                    int mk = nt * 8 + 2 * (lane & 3) + c;
                    int hk = mk >> 3, wk = mk & 7;
                    float bv = sbias[(iq - hk + 7) * 15 + (jq - wk + 7)];
                    float msk = (rid[mk] == ridn) ? 0.f : -100.f;
                    float s = acc[mt][nt][2 * h + c] * scale + bv + msk;
                    acc[mt][nt][2 * h + c] = s;
                    mx[mt][h] = fmaxf(mx[mt][h], s);
                }
        }
    #pragma unroll
    for (int mt = 0; mt < 2; mt++)
        #pragma unroll
        for (int h = 0; h < 2; h++) {
            float m0 = mx[mt][h];
            m0 = fmaxf(m0, __shfl_xor_sync(0xffffffffu, m0, 1));
            m0 = fmaxf(m0, __shfl_xor_sync(0xffffffffu, m0, 2));
            mx[mt][h] = m0;
        }
    float sum[2][2] = {{0.f, 0.f}, {0.f, 0.f}};
    #pragma unroll
    for (int mt = 0; mt < 2; mt++)
        #pragma unroll
        for (int h = 0; h < 2; h++) {
            int nq = warp * 32 + mt * 16 + (lane >> 2) + 8 * h;
            #pragma unroll
            for (int nt = 0; nt < 8; nt++) {
                float e0 = __expf(acc[mt][nt][2 * h + 0] - mx[mt][h]);
                float e1 = __expf(acc[mt][nt][2 * h + 1] - mx[mt][h]);
                sum[mt][h] += e0 + e1;
                *(__half2*)&sc[nq][nt * 8 + 2 * (lane & 3)] =
                    __floats2half2_rn(e0, e1);
            }
        }
    #pragma unroll
    for (int mt = 0; mt < 2; mt++)
        #pragma unroll
        for (int h = 0; h < 2; h++) {
            float s0 = sum[mt][h];
            s0 += __shfl_xor_sync(0xffffffffu, s0, 1);
            s0 += __shfl_xor_sync(0xffffffffu, s0, 2);
            sum[mt][h] = 1.f / s0;
        }
    __syncwarp();

    float accd[2][4][4];
    #pragma unroll
    for (int mt = 0; mt < 2; mt++)
        #pragma unroll
        for (int nt = 0; nt < 4; nt++)
            #pragma unroll
            for (int r = 0; r < 4; r++) accd[mt][nt][r] = 0.f;
    {
        uint32_t pa[2], va[2];
        int arow = warp * 32 + (lane & 15);
        int akof = (lane >> 4) * 16;
        #pragma unroll
        for (int mt = 0; mt < 2; mt++)
            pa[mt] = ssc + (uint32_t)((arow + mt * 16) * 144 + akof);
        int brow = (lane & 7) + ((lane >> 4) << 3);
        int bkof = ((lane >> 3) & 1) << 4;
        #pragma unroll
        for (int p = 0; p < 2; p++)
            va[p] = svt + (uint32_t)((brow + p * 16) * 144 + bkof);

        #pragma unroll
        for (int kk = 0; kk < 64; kk += 16) {
            uint32_t af[2][4], bf[4][2];
            #pragma unroll
            for (int mt = 0; mt < 2; mt++)
                ldsm_x4(af[mt][0], af[mt][1], af[mt][2], af[mt][3],
                        pa[mt] + kk * 2);
            #pragma unroll
            for (int p = 0; p < 2; p++)
                ldsm_x4(bf[2 * p][0], bf[2 * p][1], bf[2 * p + 1][0],
                        bf[2 * p + 1][1], va[p] + kk * 2);
            #pragma unroll
            for (int mt = 0; mt < 2; mt++)
                #pragma unroll
                for (int nt = 0; nt < 4; nt++)
                    mma_16816(accd[mt][nt], af[mt], bf[nt]);
        }
    }

    #pragma unroll
    for (int mt = 0; mt < 2; mt++)
        #pragma unroll
        for (int h = 0; h < 2; h++) {
            int nq = warp * 32 + mt * 16 + (lane >> 2) + 8 * h;
            float inv = sum[mt][h];
            __half* o = ctx + ((size_t)win * 64 + nq) * CDIM + head * 32;
            #pragma unroll
            for (int nt = 0; nt < 4; nt++) {
                int d = nt * 8 + 2 * (lane & 3);
                *(__half2*)(o + d) =
                    __floats2half2_rn(accd[mt][nt][2 * h + 0] * inv,
                                      accd[mt][nt][2 * h + 1] * inv);
            }
        }
}

// ============================ launch =======================================
extern "C" void kernel_launch(void* const* d_in, const int* in_sizes, int n_in,
                              void* d_out, int out_size) {
    const float* hid    = (const float*)d_in[0];
    const float* q_w    = (const float*)d_in[1];
    const float* q_b    = (const float*)d_in[2];
    const float* k_w    = (const float*)d_in[3];
    const float* k_b    = (const float*)d_in[4];
    const float* v_w    = (const float*)d_in[5];
    const float* v_b    = (const float*)d_in[6];
    const float* proj_w = (const float*)d_in[7];
    const float* proj_b = (const float*)d_in[8];
    const float* relb   = (const float*)d_in[9];
    const float* ln1w   = (const float*)d_in[10];
    const float* ln1b   = (const float*)d_in[11];
    const float* ln2w   = (const float*)d_in[12];
    const float* ln2b   = (const float*)d_in[13];
    const float* fc1w   = (const float*)d_in[14];
    const float* fc1b   = (const float*)d_in[15];
    const float* fc2w   = (const float*)d_in[16];
    const float* fc2b   = (const float*)d_in[17];

    unsigned char* base = nullptr;
    cudaGetSymbolAddress((void**)&base, g_scratch);
    const size_t TC = (size_t)NTOK * CDIM;
    __half* xw   = (__half*)base;
    __half* qkvb = (__half*)(base + TC * 2);
    __half* cx   = (__half*)(base + TC * 8);
    float*  hb   = (float*)(base + TC * 10);
    __half* yb   = (__half*)(base + TC * 14);
    __half* mlp  = (__half*)(base + TC * 16);
    unsigned char* wbase = base + TC * 24;
    const size_t CC = (size_t)CDIM * CDIM, MC = (size_t)MLPD * CDIM;
    __half* wqkv = (__half*)wbase;
    __half* wp   = wqkv + 3 * CC;
    __half* wf1  = wp + CC;
    __half* wf2  = wf1 + MC;
    float*  qkvbias = (float*)(wf2 + MC);

    float* out = (float*)d_out;

    cudaFuncSetAttribute(gemm_f16_kernel,
                         cudaFuncAttributeMaxDynamicSharedMemorySize, GEMM_SMEM);

    convert_weights_kernel<<<3072, 256>>>(q_w, k_w, v_w, proj_w, fc1w, fc2w,
                                          q_b, k_b, v_b,
                                          wqkv, wp, wf1, wf2, qkvbias);

    ln1_gather_kernel<<<NTOK / 8, 256>>>(hid, ln1w, ln1b, xw);

    gemm_f16_kernel<<<dim3(QKVN / BN, NTOK / BM), 256, GEMM_SMEM>>>(
        xw, wqkv, qkvbias, qkvb, QKVN, CDIM, 0, nullptr);

    attn_kernel<<<dim3(1024, NHEADS), 64>>>(qkvb, relb, cx);

    gemm_f16_kernel<<<dim3(CDIM / BN, NTOK / BM), 256, GEMM_SMEM>>>(
        cx, wp, proj_b, hb, CDIM, CDIM, 4, hid);

    ln_plain_kernel<<<NTOK / 8, 256>>>(hb, ln2w, ln2b, yb);

    gemm_f16_kernel<<<dim3(MLPD / BN, NTOK / BM), 256, GEMM_SMEM>>>(
        yb, wf1, fc1b, mlp, MLPD, CDIM, 1, nullptr);

    gemm_f16_kernel<<<dim3(CDIM / BN, NTOK / BM), 256, GEMM_SMEM>>>(
        mlp, wf2, fc2b, out, CDIM, MLPD, 2, hb);
}

// round 17
// speedup vs baseline: 1.2278x; 1.0048x over previous
#include <cuda_runtime.h>
#include <cuda_fp16.h>
#include <math.h>
#include <stdint.h>

// ---------------------------------------------------------------------------
// DonutSwinLayer: B=16, H=W=64, C=512, NH=16, HD=32, WS=8, N=64, SS=4, MLP=2048
// Round 17: drop fp32 hb buffer. proj -> half attn_out (window order);
//           LN2 fuses residual+unshift; fc2 epilogue recomputes residual.
// ---------------------------------------------------------------------------

#define NTOK   65536
#define CDIM   512
#define NHEADS 16
#define HDIM   32
#define SSH    4
#define MLPD   2048
#define QKVN   1536
#define TCH    33554432ULL          // NTOK*CDIM (halves per q/k/v plane)

#define BM 128
#define BN 128
#define BK 64
#define ROWB 144
#define A_OFF 0
#define B_OFF (BM * ROWB)
#define STAGE_B ((BM + BN) * ROWB)
#define NSTAGE 3
#define GEMM_SMEM (NSTAGE * STAGE_B)   // 110592

__device__ unsigned char g_scratch[(size_t)26 * NTOK * CDIM + (1u << 24)];

// ============================ helpers ======================================
__device__ __forceinline__ void cp_async16(uint32_t s, const void* g) {
    asm volatile("cp.async.cg.shared.global [%0], [%1], 16;" :: "r"(s), "l"(g));
}
__device__ __forceinline__ void cp_commit() {
    asm volatile("cp.async.commit_group;");
}
template<int N_> __device__ __forceinline__ void cp_wait() {
    asm volatile("cp.async.wait_group %0;" :: "n"(N_));
}
__device__ __forceinline__ void ldsm_x4(uint32_t& r0, uint32_t& r1,
                                        uint32_t& r2, uint32_t& r3, uint32_t a) {
    asm volatile("ldmatrix.sync.aligned.m8n8.x4.shared.b16 {%0,%1,%2,%3}, [%4];"
                 : "=r"(r0), "=r"(r1), "=r"(r2), "=r"(r3) : "r"(a));
}
__device__ __forceinline__ void mma_16816(float* d, const uint32_t* a,
                                          const uint32_t* b) {
    asm volatile(
        "mma.sync.aligned.m16n8k16.row.col.f32.f16.f16.f32 "
        "{%0,%1,%2,%3}, {%4,%5,%6,%7}, {%8,%9}, {%0,%1,%2,%3};\n"
        : "+f"(d[0]), "+f"(d[1]), "+f"(d[2]), "+f"(d[3])
        : "r"(a[0]), "r"(a[1]), "r"(a[2]), "r"(a[3]), "r"(b[0]), "r"(b[1]));
}

// single prepass: weights fp32->fp16 + qkv bias concat
__global__ void convert_weights_kernel(
    const float* __restrict__ qw, const float* __restrict__ kw,
    const float* __restrict__ vw, const float* __restrict__ pw,
    const float* __restrict__ f1, const float* __restrict__ f2,
    const float* __restrict__ qb, const float* __restrict__ kb,
    const float* __restrict__ vb,
    __half* __restrict__ wqkv, __half* __restrict__ wp,
    __half* __restrict__ wf1, __half* __restrict__ wf2,
    float* __restrict__ qkvbias) {
    const int CC = 262144, MC = 1048576;
    int gi = blockIdx.x * blockDim.x + threadIdx.x;
    if (gi < 1536) {
        float v = (gi < 512) ? qb[gi] : (gi < 1024 ? kb[gi - 512] : vb[gi - 1024]);
        qkvbias[gi] = v;
    }
    int i = gi * 4;
    const float* src; __half* dst; int off;
    if (i < CC)              { src = qw; dst = wqkv;          off = i; }
    else if (i < 2 * CC)     { src = kw; dst = wqkv + CC;     off = i - CC; }
    else if (i < 3 * CC)     { src = vw; dst = wqkv + 2 * CC; off = i - 2 * CC; }
    else if (i < 4 * CC)     { src = pw; dst = wp;            off = i - 3 * CC; }
    else if (i < 4 * CC + MC){ src = f1; dst = wf1;           off = i - 4 * CC; }
    else                     { src = f2; dst = wf2;           off = i - 4 * CC - MC; }
    float4 v = *(const float4*)(src + off);
    *(__half2*)(dst + off)     = __floats2half2_rn(v.x, v.y);
    *(__half2*)(dst + off + 2) = __floats2half2_rn(v.z, v.w);
}

// ============================ LN kernels (warp per row) ====================
__device__ __forceinline__ void warp_reduce_2(float& s, float& s2) {
    #pragma unroll
    for (int o = 16; o > 0; o >>= 1) {
        s  += __shfl_xor_sync(0xffffffffu, s,  o);
        s2 += __shfl_xor_sync(0xffffffffu, s2, o);
    }
}

__global__ __launch_bounds__(256)
void ln1_gather_kernel(const float* __restrict__ hid,
                       const float* __restrict__ g,
                       const float* __restrict__ b,
                       __half* __restrict__ xw) {
    int wr = blockIdx.x * 8 + (threadIdx.x >> 5);
    int lane = threadIdx.x & 31;
    int b_  = wr >> 12;
    int rem = wr & 4095;
    int wi  = rem >> 6;
    int n   = rem & 63;
    int wh = wi >> 3, ww = wi & 7;
    int i  = n  >> 3, j  = n  & 7;
    int sh_ = ((wh * 8 + i) + SSH) & 63;
    int sw_ = ((ww * 8 + j) + SSH) & 63;
    const float* src = hid + ((size_t)b_ * 4096 + sh_ * 64 + sw_) * CDIM;

    float4 v[4];
    float s = 0.f, s2 = 0.f;
    #pragma unroll
    for (int u = 0; u < 4; u++) {
        v[u] = *(const float4*)(src + lane * 4 + u * 128);
        s  += v[u].x + v[u].y + v[u].z + v[u].w;
        s2 += v[u].x * v[u].x + v[u].y * v[u].y + v[u].z * v[u].z + v[u].w * v[u].w;
    }
    warp_reduce_2(s, s2);
    float mu  = s * (1.f / CDIM);
    float var = s2 * (1.f / CDIM) - mu * mu;
    float inv = rsqrtf(var + 1e-5f);

    __half* dst = xw + (size_t)wr * CDIM;
    #pragma unroll
    for (int u = 0; u < 4; u++) {
        int c = lane * 4 + u * 128;
        float4 gg = *(const float4*)(g + c);
        float4 bb = *(const float4*)(b + c);
        __half2 h0 = __floats2half2_rn((v[u].x - mu) * inv * gg.x + bb.x,
                                       (v[u].y - mu) * inv * gg.y + bb.y);
        __half2 h1 = __floats2half2_rn((v[u].z - mu) * inv * gg.z + bb.z,
                                       (v[u].w - mu) * inv * gg.w + bb.w);
        *(__half2*)(dst + c)     = h0;
        *(__half2*)(dst + c + 2) = h1;
    }
}

// LN2 fused with residual + unshift: per WINDOW row wr, h = hid[g(wr)] + po[wr],
// LN(h) -> yb[g(wr)] (half).
__global__ __launch_bounds__(256)
void ln2_fused_kernel(const float* __restrict__ hid,
                      const __half* __restrict__ po,
                      const float* __restrict__ g,
                      const float* __restrict__ b,
                      __half* __restrict__ yb) {
    int wr = blockIdx.x * 8 + (threadIdx.x >> 5);
    int lane = threadIdx.x & 31;
    int b_  = wr >> 12;
    int rem = wr & 4095;
    int wi  = rem >> 6;
    int n   = rem & 63;
    int wh = wi >> 3, ww = wi & 7;
    int i  = n  >> 3, j  = n  & 7;
    int sh_ = ((wh * 8 + i) + SSH) & 63;
    int sw_ = ((ww * 8 + j) + SSH) & 63;
    size_t grow = (size_t)b_ * 4096 + sh_ * 64 + sw_;
    const float*  hsrc = hid + grow * CDIM;
    const __half* psrc = po + (size_t)wr * CDIM;

    float4 v[4];
    float s = 0.f, s2 = 0.f;
    #pragma unroll
    for (int u = 0; u < 4; u++) {
        int c = lane * 4 + u * 128;
        float4 hv = *(const float4*)(hsrc + c);
        __half2 p0 = *(const __half2*)(psrc + c);
        __half2 p1 = *(const __half2*)(psrc + c + 2);
        float2 f0 = __half22float2(p0);
        float2 f1 = __half22float2(p1);
        v[u].x = hv.x + f0.x; v[u].y = hv.y + f0.y;
        v[u].z = hv.z + f1.x; v[u].w = hv.w + f1.y;
        s  += v[u].x + v[u].y + v[u].z + v[u].w;
        s2 += v[u].x * v[u].x + v[u].y * v[u].y + v[u].z * v[u].z + v[u].w * v[u].w;
    }
    warp_reduce_2(s, s2);
    float mu  = s * (1.f / CDIM);
    float var = s2 * (1.f / CDIM) - mu * mu;
    float inv = rsqrtf(var + 1e-5f);
    __half* dst = yb + grow * CDIM;
    #pragma unroll
    for (int u = 0; u < 4; u++) {
        int c = lane * 4 + u * 128;
        float4 gg = *(const float4*)(g + c);
        float4 bb = *(const float4*)(b + c);
        __half2 h0 = __floats2half2_rn((v[u].x - mu) * inv * gg.x + bb.x,
                                       (v[u].y - mu) * inv * gg.y + bb.y);
        __half2 h1 = __floats2half2_rn((v[u].z - mu) * inv * gg.z + bb.z,
                                       (v[u].w - mu) * inv * gg.w + bb.w);
        *(__half2*)(dst + c)     = h0;
        *(__half2*)(dst + c + 2) = h1;
    }
}

// ============================ fp16 GEMM ====================================
// mode: 0 qkv head-major scatter (half), 1 gelu->half, 5 plain half,
//       6 f32 out + residual hid[row] + half po[wr(row)]
__global__ __launch_bounds__(256, 2)
void gemm_f16_kernel(const __half* __restrict__ A, const __half* __restrict__ W,
                     const float* __restrict__ bias, void* __restrict__ Cout,
                     int N, int K, int mode, const float* __restrict__ add,
                     const __half* __restrict__ addh) {
    extern __shared__ char smem[];
    uint32_t sb = (uint32_t)__cvta_generic_to_shared(smem);

    const int tid  = threadIdx.x;
    const int warp = tid >> 5;
    const int lane = tid & 31;
    const int bm   = blockIdx.y * BM;
    const int bn   = blockIdx.x * BN;
    const int wm   = (warp & 3) * 32;
    const int wn   = (warp >> 2) * 64;
    const int lr   = lane >> 2;
    const int lc   = lane & 3;

    uint32_t aAddr[2], bAddr[4];
    {
        int arow = wm + (lane & 15);
        int akof = (lane >> 4) * 16;
        #pragma unroll
        for (int mt = 0; mt < 2; mt++)
            aAddr[mt] = sb + A_OFF + (uint32_t)((arow + mt * 16) * ROWB + akof);
        int brow = wn + (lane & 7) + ((lane >> 4) << 3);
        int bkof = ((lane >> 3) & 1) << 4;
        #pragma unroll
        for (int p = 0; p < 4; p++)
            bAddr[p] = sb + B_OFF + (uint32_t)((brow + p * 16) * ROWB + bkof);
    }

    float acc[2][8][4];
    #pragma unroll
    for (int mt = 0; mt < 2; mt++)
        #pragma unroll
        for (int nt = 0; nt < 8; nt++)
            #pragma unroll
            for (int r = 0; r < 4; r++) acc[mt][nt][r] = 0.f;

    const int KT = K / BK;

    auto load_tile = [&](int buf, int k0) {
        uint32_t sbase = sb + (uint32_t)(buf * STAGE_B);
        #pragma unroll
        for (int u = 0; u < 4; u++) {
            int ch = tid + u * 256;
            int row = ch >> 3, kq = ch & 7;
            cp_async16(sbase + A_OFF + (uint32_t)(row * ROWB + kq * 16),
                       A + (size_t)(bm + row) * K + k0 + kq * 8);
        }
        #pragma unroll
        for (int u = 0; u < 4; u++) {
            int ch = tid + u * 256;
            int row = ch >> 3, kq = ch & 7;
            cp_async16(sbase + B_OFF + (uint32_t)(row * ROWB + kq * 16),
                       W + (size_t)(bn + row) * K + k0 + kq * 8);
        }
        cp_commit();
    };

    load_tile(0, 0);
    load_tile(1, BK);

    int buf = 0;
    for (int kt = 0; kt < KT; kt++) {
        if (kt < KT - 1) cp_wait<1>(); else cp_wait<0>();
        __syncthreads();
        if (kt + 2 < KT) {
            int nb = buf + 2; if (nb >= NSTAGE) nb -= NSTAGE;
            load_tile(nb, (kt + 2) * BK);
        }

        uint32_t soff = (uint32_t)(buf * STAGE_B);
        #pragma unroll
        for (int ks = 0; ks < BK; ks += 16) {
            uint32_t af[2][4], bf[8][2];
            #pragma unroll
            for (int mt = 0; mt < 2; mt++)
                ldsm_x4(af[mt][0], af[mt][1], af[mt][2], af[mt][3],
                        aAddr[mt] + soff + ks * 2);
            #pragma unroll
            for (int p = 0; p < 4; p++)
                ldsm_x4(bf[2 * p][0], bf[2 * p][1], bf[2 * p + 1][0],
                        bf[2 * p + 1][1], bAddr[p] + soff + ks * 2);
            #pragma unroll
            for (int mt = 0; mt < 2; mt++)
                #pragma unroll
                for (int nt = 0; nt < 8; nt++)
                    mma_16816(acc[mt][nt], af[mt], bf[nt]);
        }
        buf++; if (buf >= NSTAGE) buf = 0;
    }

    // epilogue
    #pragma unroll
    for (int mt = 0; mt < 2; mt++) {
        #pragma unroll
        for (int h = 0; h < 2; h++) {
            int row = bm + wm + mt * 16 + lr + h * 8;
            size_t wrow = (size_t)row;
            if (mode == 6) {
                // inverse map: global row -> window row
                int b_ = row >> 12, y = (row >> 6) & 63, x = row & 63;
                int yw = (y - SSH) & 63, xw_ = (x - SSH) & 63;
                wrow = (size_t)b_ * 4096 +
                       ((yw >> 3) * 8 + (xw_ >> 3)) * 64 +
                       ((yw & 7) * 8 + (xw_ & 7));
            }
            #pragma unroll
            for (int nt = 0; nt < 8; nt++) {
                int col = bn + wn + nt * 8 + 2 * lc;
                float v0 = acc[mt][nt][2 * h + 0] + bias[col];
                float v1 = acc[mt][nt][2 * h + 1] + bias[col + 1];
                if (mode == 0) {
                    int which = col >> 9;
                    int hc = col & 511;
                    int head = hc >> 5, d = hc & 31;
                    size_t off = (size_t)which * TCH +
                        ((((size_t)(row >> 6) * NHEADS + head) * 64) +
                         (row & 63)) * 32 + d;
                    *(__half2*)((__half*)Cout + off) = __floats2half2_rn(v0, v1);
                } else if (mode == 1) {
                    v0 = 0.5f * v0 * (1.f + erff(v0 * 0.70710678118654752f));
                    v1 = 0.5f * v1 * (1.f + erff(v1 * 0.70710678118654752f));
                    __half* crow = (__half*)Cout + (size_t)row * N + col;
                    *(__half2*)crow = __floats2half2_rn(v0, v1);
                } else if (mode == 5) {
                    __half* crow = (__half*)Cout + (size_t)row * N + col;
                    *(__half2*)crow = __floats2half2_rn(v0, v1);
                } else {  // mode 6
                    const float* hr = add + (size_t)row * N + col;
                    float2 pf = __half22float2(
                        *(const __half2*)(addh + wrow * N + col));
                    v0 += hr[0] + pf.x;
                    v1 += hr[1] + pf.y;
                    float* crow = (float*)Cout + (size_t)row * N + col;
                    crow[0] = v0; crow[1] = v1;
                }
            }
        }
    }
}

// ============================ attention (tensor core, R15) =================
__global__ __launch_bounds__(64, 9)
void attn_kernel(const __half* __restrict__ qkv, const float* __restrict__ btab,
                 __half* __restrict__ ctx) {
    __shared__ __align__(16) __half qs[64][40];
    __shared__ __align__(16) __half ks[64][40];
    __shared__ __align__(16) __half vt[32][72];
    __shared__ __align__(16) __half sc[64][72];
    __shared__ float sbias[225];
    __shared__ int   rid[64];

    int win  = blockIdx.x;
    int head = blockIdx.y;
    int tid  = threadIdx.x;
    int warp = tid >> 5;
    int lane = tid & 31;
    int n    = tid;

    int wi = win & 63;
    int wh = wi >> 3, ww = wi & 7;
    {
        int i = n >> 3, j = n & 7;
        int hs = wh * 8 + i, wc = ww * 8 + j;
        int rh = (hs < 56) ? 0 : ((hs < 60) ? 1 : 2);
        int rw = (wc < 56) ? 0 : ((wc < 60) ? 1 : 2);
        rid[n] = rh * 3 + rw;
    }

    size_t hbase = (((size_t)win * NHEADS + head) * 64) * 32;
    {
        const uint4* qp = (const uint4*)(qkv + hbase + (size_t)n * 32);
        const uint4* kp = (const uint4*)(qkv + TCH + hbase + (size_t)n * 32);
        #pragma unroll
        for (int u = 0; u < 4; u++) {
            ((uint4*)qs[n])[u] = qp[u];
            ((uint4*)ks[n])[u] = kp[u];
        }
        const uint4* vp = (const uint4*)(qkv + 2 * TCH + hbase + (size_t)n * 32);
        __half vr[32];
        #pragma unroll
        for (int u = 0; u < 4; u++) ((uint4*)vr)[u] = vp[u];
        #pragma unroll
        for (int d = 0; d < 32; d++) vt[d][n] = vr[d];
    }
    for (int t = tid; t < 225; t += 64) sbias[t] = btab[t * NHEADS + head];
    __syncthreads();

    uint32_t sqs = (uint32_t)__cvta_generic_to_shared(qs);
    uint32_t sks = (uint32_t)__cvta_generic_to_shared(ks);
    uint32_t svt = (uint32_t)__cvta_generic_to_shared(vt);
    uint32_t ssc = (uint32_t)__cvta_generic_to_shared(sc);

    float acc[2][8][4];
    #pragma unroll
    for (int mt = 0; mt < 2; mt++)
        #pragma unroll
        for (int nt = 0; nt < 8; nt++)
            #pragma unroll
            for (int r = 0; r < 4; r++) acc[mt][nt][r] = 0.f;
    {
        uint32_t qa[2], ka[4];
        int arow = warp * 32 + (lane & 15);
        int akof = (lane >> 4) * 16;
        #pragma unroll
        for (int mt = 0; mt < 2; mt++)
            qa[mt] = sqs + (uint32_t)((arow + mt * 16) * 80 + akof);
        int brow = (lane & 7) + ((lane >> 4) << 3);
        int bkof = ((lane >> 3) & 1) << 4;
        #pragma unroll
        for (int p = 0; p < 4; p++)
            ka[p] = sks + (uint32_t)((brow + p * 16) * 80 + bkof);

        #pragma unroll
        for (int kk = 0; kk < 32; kk += 16) {
            uint32_t af[2][4], bf[8][2];
            #pragma unroll
            for (int mt = 0; mt < 2; mt++)
                ldsm_x4(af[mt][0], af[mt][1], af[mt][2], af[mt][3],
                        qa[mt] + kk * 2);
            #pragma unroll
            for (int p = 0; p < 4; p++)
                ldsm_x4(bf[2 * p][0], bf[2 * p][1], bf[2 * p + 1][0],
                        bf[2 * p + 1][1], ka[p] + kk * 2);
            #pragma unroll
            for (int mt = 0; mt < 2; mt++)
                #pragma unroll
                for (int nt = 0; nt < 8; nt++)
                    mma_16816(acc[mt][nt], af[mt], bf[nt]);
        }
    }

    const float scale = 0.17677669529663687f;
    float mx[2][2] = {{-1e30f, -1e30f}, {-1e30f, -1e30f}};
    #pragma unroll
    for (int mt = 0; mt < 2; mt++)
        #pragma unroll
        for (int h = 0; h < 2; h++) {
            int nq = warp * 32 + mt * 16 + (lane >> 2) + 8 * h;
            int iq = nq >> 3, jq = nq & 7;
            int ridn = rid[nq];
            #pragma unroll
            for (int nt = 0; nt < 8; nt++)
                #pragma unroll
                for (int c = 0; c < 2; c++) {
                    int mk = nt * 8 + 2 * (lane & 3) + c;
                    int hk = mk >> 3, wk = mk & 7;
                    float bv = sbias[(iq - hk + 7) * 15 + (jq - wk + 7)];
                    float msk = (rid[mk] == ridn) ? 0.f : -100.f;
                    float s = acc[mt][nt][2 * h + c] * scale + bv + msk;
                    acc[mt][nt][2 * h + c] = s;
                    mx[mt][h] = fmaxf(mx[mt][h], s);
                }
        }
    #pragma unroll
    for (int mt = 0; mt < 2; mt++)
        #pragma unroll
        for (int h = 0; h < 2; h++) {
            float m0 = mx[mt][h];
            m0 = fmaxf(m0, __shfl_xor_sync(0xffffffffu, m0, 1));
            m0 = fmaxf(m0, __shfl_xor_sync(0xffffffffu, m0, 2));
            mx[mt][h] = m0;
        }
    float sum[2][2] = {{0.f, 0.f}, {0.f, 0.f}};
    #pragma unroll
    for (int mt = 0; mt < 2; mt++)
        #pragma unroll
        for (int h = 0; h < 2; h++) {
            int nq = warp * 32 + mt * 16 + (lane >> 2) + 8 * h;
            #pragma unroll
            for (int nt = 0; nt < 8; nt++) {
                float e0 = __expf(acc[mt][nt][2 * h + 0] - mx[mt][h]);
                float e1 = __expf(acc[mt][nt][2 * h + 1] - mx[mt][h]);
                sum[mt][h] += e0 + e1;
                *(__half2*)&sc[nq][nt * 8 + 2 * (lane & 3)] =
                    __floats2half2_rn(e0, e1);
            }
        }
    #pragma unroll
    for (int mt = 0; mt < 2; mt++)
        #pragma unroll
        for (int h = 0; h < 2; h++) {
            float s0 = sum[mt][h];
            s0 += __shfl_xor_sync(0xffffffffu, s0, 1);
            s0 += __shfl_xor_sync(0xffffffffu, s0, 2);
            sum[mt][h] = 1.f / s0;
        }
    __syncwarp();

    float accd[2][4][4];
    #pragma unroll
    for (int mt = 0; mt < 2; mt++)
        #pragma unroll
        for (int nt = 0; nt < 4; nt++)
            #pragma unroll
            for (int r = 0; r < 4; r++) accd[mt][nt][r] = 0.f;
    {
        uint32_t pa[2], va[2];
        int arow = warp * 32 + (lane & 15);
        int akof = (lane >> 4) * 16;
        #pragma unroll
        for (int mt = 0; mt < 2; mt++)
            pa[mt] = ssc + (uint32_t)((arow + mt * 16) * 144 + akof);
        int brow = (lane & 7) + ((lane >> 4) << 3);
        int bkof = ((lane >> 3) & 1) << 4;
        #pragma unroll
        for (int p = 0; p < 2; p++)
            va[p] = svt + (uint32_t)((brow + p * 16) * 144 + bkof);

        #pragma unroll
        for (int kk = 0; kk < 64; kk += 16) {
            uint32_t af[2][4], bf[4][2];
            #pragma unroll
            for (int mt = 0; mt < 2; mt++)
                ldsm_x4(af[mt][0], af[mt][1], af[mt][2], af[mt][3],
                        pa[mt] + kk * 2);
            #pragma unroll
            for (int p = 0; p < 2; p++)
                ldsm_x4(bf[2 * p][0], bf[2 * p][1], bf[2 * p + 1][0],
                        bf[2 * p + 1][1], va[p] + kk * 2);
            #pragma unroll
            for (int mt = 0; mt < 2; mt++)
                #pragma unroll
                for (int nt = 0; nt < 4; nt++)
                    mma_16816(accd[mt][nt], af[mt], bf[nt]);
        }
    }

    #pragma unroll
    for (int mt = 0; mt < 2; mt++)
        #pragma unroll
        for (int h = 0; h < 2; h++) {
            int nq = warp * 32 + mt * 16 + (lane >> 2) + 8 * h;
            float inv = sum[mt][h];
            __half* o = ctx + ((size_t)win * 64 + nq) * CDIM + head * 32;
            #pragma unroll
            for (int nt = 0; nt < 4; nt++) {
                int d = nt * 8 + 2 * (lane & 3);
                *(__half2*)(o + d) =
                    __floats2half2_rn(accd[mt][nt][2 * h + 0] * inv,
                                      accd[mt][nt][2 * h + 1] * inv);
            }
        }
}

// ============================ launch =======================================
extern "C" void kernel_launch(void* const* d_in, const int* in_sizes, int n_in,
                              void* d_out, int out_size) {
    const float* hid    = (const float*)d_in[0];
    const float* q_w    = (const float*)d_in[1];
    const float* q_b    = (const float*)d_in[2];
    const float* k_w    = (const float*)d_in[3];
    const float* k_b    = (const float*)d_in[4];
    const float* v_w    = (const float*)d_in[5];
    const float* v_b    = (const float*)d_in[6];
    const float* proj_w = (const float*)d_in[7];
    const float* proj_b = (const float*)d_in[8];
    const float* relb   = (const float*)d_in[9];
    const float* ln1w   = (const float*)d_in[10];
    const float* ln1b   = (const float*)d_in[11];
    const float* ln2w   = (const float*)d_in[12];
    const float* ln2b   = (const float*)d_in[13];
    const float* fc1w   = (const float*)d_in[14];
    const float* fc1b   = (const float*)d_in[15];
    const float* fc2w   = (const float*)d_in[16];
    const float* fc2b   = (const float*)d_in[17];

    unsigned char* base = nullptr;
    cudaGetSymbolAddress((void**)&base, g_scratch);
    const size_t TC = (size_t)NTOK * CDIM;
    __half* xw   = (__half*)base;                  // 2TC bytes
    __half* qkvb = (__half*)(base + TC * 2);       // 6TC bytes
    __half* cx   = (__half*)(base + TC * 8);       // 2TC bytes
    __half* po   = (__half*)(base + TC * 10);      // 2TC bytes (half attn_out)
    __half* yb   = (__half*)(base + TC * 12);      // 2TC bytes
    __half* mlp  = (__half*)(base + TC * 14);      // 8TC bytes
    unsigned char* wbase = base + TC * 22;
    const size_t CC = (size_t)CDIM * CDIM, MC = (size_t)MLPD * CDIM;
    __half* wqkv = (__half*)wbase;
    __half* wp   = wqkv + 3 * CC;
    __half* wf1  = wp + CC;
    __half* wf2  = wf1 + MC;
    float*  qkvbias = (float*)(wf2 + MC);

    float* out = (float*)d_out;

    cudaFuncSetAttribute(gemm_f16_kernel,
                         cudaFuncAttributeMaxDynamicSharedMemorySize, GEMM_SMEM);

    convert_weights_kernel<<<3072, 256>>>(q_w, k_w, v_w, proj_w, fc1w, fc2w,
                                          q_b, k_b, v_b,
                                          wqkv, wp, wf1, wf2, qkvbias);

    ln1_gather_kernel<<<NTOK / 8, 256>>>(hid, ln1w, ln1b, xw);

    gemm_f16_kernel<<<dim3(QKVN / BN, NTOK / BM), 256, GEMM_SMEM>>>(
        xw, wqkv, qkvbias, qkvb, QKVN, CDIM, 0, nullptr, nullptr);

    attn_kernel<<<dim3(1024, NHEADS), 64>>>(qkvb, relb, cx);

    // proj -> half attn_out, window order
    gemm_f16_kernel<<<dim3(CDIM / BN, NTOK / BM), 256, GEMM_SMEM>>>(
        cx, wp, proj_b, po, CDIM, CDIM, 5, nullptr, nullptr);

    // LN2 fused with residual + unshift
    ln2_fused_kernel<<<NTOK / 8, 256>>>(hid, po, ln2w, ln2b, yb);

    gemm_f16_kernel<<<dim3(MLPD / BN, NTOK / BM), 256, GEMM_SMEM>>>(
        yb, wf1, fc1b, mlp, MLPD, CDIM, 1, nullptr, nullptr);

    // fc2 + recomputed residual (hid + po) -> fp32 output
    gemm_f16_kernel<<<dim3(CDIM / BN, NTOK / BM), 256, GEMM_SMEM>>>(
        mlp, wf2, fc2b, out, CDIM, MLPD, 6, hid, po);
}